// round 9
// baseline (speedup 1.0000x reference)
#include <cuda_runtime.h>
#include <cuda_bf16.h>
#include <cstdint>
#include <cstddef>

// ---------------- problem dims ----------------
#define BS 4096
#define IN 2056
#define MF 24
#define H 4
#define HE 128
#define E 64
#define NA 128
#define RNN 256
#define KTOT 8192         // E*NA
#define KF 2080           // front K in uint32 (bf16x2 pairs), 65 chunks of 32

// ---------------- scratch (device globals; no allocs allowed) ----------------
__device__ float g_hid[BS * 192];
__device__ float g_bt[BS];
__device__ float g_q[BS * H * E];
__device__ float g_km[BS * H * E];
__device__ float g_vm[BS * H * E];
__device__ float g_te[BS * 64];    // (q @ Wke^T)/8, [b][h*16+d]
__device__ float g_ta[BS * 64];    // (q @ Wka^T)/8
__device__ float g_S[RNN];
// A for final GEMM, layout [b][na*64+e]  (PERMUTED k-index)
__device__ __align__(16) __nv_bfloat16 g_Abf[(size_t)BS * KTOT];
// Wf in bf16, same permuted layout
__device__ __align__(16) __nv_bfloat16 g_Wfbf[(size_t)RNN * KTOT];
// flattened value weights: [sel][e][h*16+d]
__device__ __align__(16) __nv_bfloat16 g_Wvbf[2 * 64 * 64];
// front weights [pass 0=hi,1=lo][192][KF] uint32 (pad cols stay zero)
__device__ __align__(16) uint32_t g_WB[(size_t)2 * 192 * KF];

// ---------------- PTX helpers ----------------
__device__ __forceinline__ uint32_t smem_u32(const void* p) {
    uint32_t a;
    asm("{ .reg .u64 t; cvta.to.shared.u64 t, %1; cvt.u32.u64 %0, t; }" : "=r"(a) : "l"(p));
    return a;
}
__device__ __forceinline__ void cp16(uint32_t dst, const void* src) {
    asm volatile("cp.async.cg.shared.global [%0], [%1], 16;" :: "r"(dst), "l"(src) : "memory");
}
#define CP_COMMIT() asm volatile("cp.async.commit_group;" ::: "memory")
#define CP_WAIT(n)  asm volatile("cp.async.wait_group %0;" :: "n"(n) : "memory")

#define LDSM_X4(r0, r1, r2, r3, addr) \
    asm volatile("ldmatrix.sync.aligned.m8n8.x4.shared.b16 {%0,%1,%2,%3}, [%4];" \
                 : "=r"(r0), "=r"(r1), "=r"(r2), "=r"(r3) : "r"(addr))

#define MMA16816(d, a, b) \
    asm volatile("mma.sync.aligned.m16n8k16.row.col.f32.bf16.bf16.f32 " \
                 "{%0,%1,%2,%3}, {%4,%5,%6,%7}, {%8,%9}, {%0,%1,%2,%3};" \
                 : "+f"((d)[0]), "+f"((d)[1]), "+f"((d)[2]), "+f"((d)[3]) \
                 : "r"((a)[0]), "r"((a)[1]), "r"((a)[2]), "r"((a)[3]), \
                   "r"((b)[0]), "r"((b)[1]))

#define SWZ(x) ((x) ^ (((x) >> 3) & 0x70))

__device__ __forceinline__ uint32_t packbf2(float x, float y) {
    __nv_bfloat162 p = __floats2bfloat162_rn(x, y);
    return *(uint32_t*)&p;
}

// =====================================================================
// K0: prep — blocks 0..255: Wf row -> permuted bf16 + S[r]
//           block 256: flatten Wve/Wva
//           blocks 257..448: front weights hi/lo
// =====================================================================
__global__ __launch_bounds__(256) void k_prep(const float* __restrict__ Wf,
                                              const float* __restrict__ Wve,
                                              const float* __restrict__ Wva,
                                              const float* __restrict__ Wb1,
                                              const float* __restrict__ Wh1) {
    int r = blockIdx.x;
    int tid = threadIdx.x;
    if (r < 256) {
        __shared__ float row[8256];
        __shared__ float red[8];
        float s = 0.f;
        for (int i = tid; i < 8192; i += 256) {
            float v = Wf[(size_t)r * 8192 + i];
            row[i + (i >> 7)] = v;
            s += v;
        }
        #pragma unroll
        for (int o = 16; o; o >>= 1) s += __shfl_xor_sync(0xffffffffu, s, o);
        if ((tid & 31) == 0) red[tid >> 5] = s;
        __syncthreads();
        if (tid == 0) {
            float t = 0.f;
            #pragma unroll
            for (int j = 0; j < 8; j++) t += red[j];
            g_S[r] = t;
        }
        for (int i = tid; i < 8192; i += 256) {
            int na = i >> 6, e = i & 63;
            int src = e * 128 + na;
            g_Wfbf[(size_t)r * 8192 + i] = __float2bfloat16_rn(row[src + (src >> 7)]);
        }
    } else if (r == 256) {
        for (int i = tid; i < 8192; i += 256) {
            int sel = i >> 12, j = i & 4095;
            int e = j >> 6, hd = j & 63, h = hd >> 4, d = hd & 15;
            const float* W = sel ? Wva : Wve;
            g_Wvbf[i] = __float2bfloat16_rn(W[h * 1024 + e * 16 + d]);
        }
    } else {
        int n = r - 257;   // 0..191
        const float* W = (n < 64) ? (Wb1 + (size_t)n * IN) : (Wh1 + (size_t)(n - 64) * IN);
        uint32_t* d0 = g_WB + (size_t)n * KF;
        uint32_t* d1 = g_WB + (size_t)192 * KF + (size_t)n * KF;
        for (int k = tid; k < IN; k += 256) {
            float x = W[k];
            __nv_bfloat16 hi = __float2bfloat16_rn(x);
            __nv_bfloat16 lo = __float2bfloat16_rn(x - __bfloat162float(hi));
            __nv_bfloat162 p0; p0.x = hi; p0.y = hi;
            __nv_bfloat162 p1; p1.x = lo; p1.y = lo;
            d0[k] = *(uint32_t*)&p0;
            d1[k] = *(uint32_t*)&p1;
        }
    }
}

// =====================================================================
// K1: front GEMM (tensor, split-bf16 exact), obs converted in-register:
//     g_hid[4096,192] = relu(obs @ [Wb1;Wh1]^T + bias)
// =====================================================================
__global__ __launch_bounds__(256) void k_front_tc(const float* __restrict__ obs,
                                                  const float* __restrict__ bb1,
                                                  const float* __restrict__ bh1) {
    __shared__ __align__(128) char sm8[49152];
    const uint32_t sb = smem_u32(sm8);
    const int tid = threadIdx.x, lane = tid & 31, w = tid >> 5;
    const int bm = blockIdx.x * 64, bn = blockIdx.y * 64;
    const int wm = (w & 3) * 16, wn = (w >> 2) * 32;
    float d[4][4] = {};

    auto stageA = [&](int t, int buf) {
        #pragma unroll
        for (int i = 0; i < 2; i++) {
            int idx = tid + 256 * i;
            int row = idx >> 3, c16 = idx & 7;
            int k0 = t * 32 + c16 * 4;
            float4 v = make_float4(0.f, 0.f, 0.f, 0.f);
            if (k0 < IN) v = *(const float4*)(obs + (size_t)(bm + row) * IN + k0);
            uint32_t p[4];
            {
                float xs[4] = {v.x, v.y, v.z, v.w};
                #pragma unroll
                for (int j = 0; j < 4; j++) {
                    __nv_bfloat16 hi = __float2bfloat16_rn(xs[j]);
                    __nv_bfloat16 lo = __float2bfloat16_rn(xs[j] - __bfloat162float(hi));
                    __nv_bfloat162 pr; pr.x = hi; pr.y = lo;
                    p[j] = *(uint32_t*)&pr;
                }
            }
            *(uint4*)(sm8 + buf * 8192 + SWZ((uint32_t)(row * 128 + c16 * 16))) = *(uint4*)p;
        }
    };
    auto stageB = [&](int t, int buf) {
        #pragma unroll
        for (int i = 0; i < 2; i++) {
            int idx = tid + 256 * i;
            int row = idx >> 3, c16 = idx & 7;
            const uint32_t* s0 = g_WB + (size_t)(bn + row) * KF + t * 32 + c16 * 4;
            uint32_t off = SWZ((uint32_t)(row * 128 + c16 * 16));
            cp16(sb + 16384 + buf * 8192 + off, s0);
            cp16(sb + 32768 + buf * 8192 + off, s0 + (size_t)192 * KF);
        }
        CP_COMMIT();
    };

    stageA(0, 0);
    stageB(0, 0);
    for (int t = 0; t < 65; t++) {
        const int buf = t & 1;
        if (t < 64) {
            stageA(t + 1, buf ^ 1);
            stageB(t + 1, buf ^ 1);
            CP_WAIT(1);
        } else {
            CP_WAIT(0);
        }
        __syncthreads();
        const uint32_t ab = sb + buf * 8192;
        const uint32_t b0b = sb + 16384 + buf * 8192;
        const uint32_t b1b = sb + 32768 + buf * 8192;
        #pragma unroll
        for (int ks = 0; ks < 4; ks++) {
            uint32_t a[4];
            uint32_t byte = (uint32_t)((wm + (lane & 15)) * 128 + (lane >> 4) * 16 + ks * 32);
            LDSM_X4(a[0], a[1], a[2], a[3], ab + SWZ(byte));
            uint32_t b0[4][2], b1[4][2];
            #pragma unroll
            for (int nr = 0; nr < 2; nr++) {
                uint32_t by2 = (uint32_t)((wn + nr * 16 + (lane & 15)) * 128
                                          + (lane >> 4) * 16 + ks * 32);
                uint32_t r0, r1, r2, r3;
                LDSM_X4(r0, r1, r2, r3, b0b + SWZ(by2));
                b0[nr * 2][0] = r0; b0[nr * 2][1] = r2;
                b0[nr * 2 + 1][0] = r1; b0[nr * 2 + 1][1] = r3;
                LDSM_X4(r0, r1, r2, r3, b1b + SWZ(by2));
                b1[nr * 2][0] = r0; b1[nr * 2][1] = r2;
                b1[nr * 2 + 1][0] = r1; b1[nr * 2 + 1][1] = r3;
            }
            #pragma unroll
            for (int nt = 0; nt < 4; nt++) {
                MMA16816(d[nt], a, b0[nt]);
                MMA16816(d[nt], a, b1[nt]);
            }
        }
        __syncthreads();
    }

    #pragma unroll
    for (int half = 0; half < 2; half++) {
        int row = bm + wm + half * 8 + (lane >> 2);
        #pragma unroll
        for (int nt = 0; nt < 4; nt++) {
            int n = bn + wn + nt * 8 + (lane & 3) * 2;
            float bias0 = (n < 64) ? bb1[n] : bh1[n - 64];
            float bias1 = (n + 1 < 64) ? bb1[n + 1] : bh1[n + 1 - 64];
            float v0 = fmaxf(d[nt][half * 2 + 0] + bias0, 0.f);
            float v1 = fmaxf(d[nt][half * 2 + 1] + bias1, 0.f);
            *(float2*)&g_hid[row * 192 + n] = make_float2(v0, v1);
        }
    }
}

// =====================================================================
// K3: fused m-MLPs (stage1 FFMA -> smem bf16, stage2 mma) -> g_q/g_km/g_vm
//     mlp==0 CTAs additionally compute te/ta = (q @ Wk^T)/8 via mma.
// =====================================================================
__global__ __launch_bounds__(256) void k_mlp(const float* __restrict__ obs,
                                             const float* __restrict__ Wq1, const float* __restrict__ bq1,
                                             const float* __restrict__ Wq2,
                                             const float* __restrict__ Wkm1, const float* __restrict__ bkm1,
                                             const float* __restrict__ Wkm2,
                                             const float* __restrict__ Wvm1, const float* __restrict__ bvm1,
                                             const float* __restrict__ Wvm2,
                                             const float* __restrict__ Wke,
                                             const float* __restrict__ Wka) {
    extern __shared__ __align__(128) char smp[];
    float* msm = (float*)smp;
    float* w1s = (float*)(smp + 12800);
    float* b1s = (float*)(smp + 25600);
    char* h1B = smp + 26112;
    char* w2B = smp + 58880;

    const int tid = threadIdx.x, lane = tid & 31;
    const int bm = blockIdx.x * 128;
    const int mlp = blockIdx.y >> 2, h = blockIdx.y & 3;
    const float* W1 = ((mlp == 0) ? Wq1 : (mlp == 1) ? Wkm1 : Wvm1) + h * HE * MF;
    const float* B1 = ((mlp == 0) ? bq1 : (mlp == 1) ? bkm1 : bvm1) + h * HE;
    const float* W2 = ((mlp == 0) ? Wq2 : (mlp == 1) ? Wkm2 : Wvm2) + h * E * HE;
    float* outp = (mlp == 0) ? g_q : (mlp == 1) ? g_km : g_vm;

    for (int i = tid; i < 128 * 24; i += 256) {
        int r = i / 24, f = i - r * 24;
        int col = (f < 4) ? f : (2032 + f);
        msm[r * 25 + f] = obs[(size_t)(bm + r) * IN + col];
    }
    for (int i = tid; i < 128 * 24; i += 256) {
        int g = i / 24, f = i - g * 24;
        w1s[g * 25 + f] = W1[g * 24 + f];
    }
    if (tid < 128) b1s[tid] = B1[tid];
    for (int i = tid; i < 1024; i += 256) {
        int e = i >> 4, g8 = (i & 15) * 8;
        int kk = g8 >> 6, wi = g8 & 63;
        const float* src = W2 + e * HE + g8;
        float4 v0 = *(const float4*)src;
        float4 v1 = *(const float4*)(src + 4);
        __nv_bfloat162 p[4];
        p[0] = __floats2bfloat162_rn(v0.x, v0.y);
        p[1] = __floats2bfloat162_rn(v0.z, v0.w);
        p[2] = __floats2bfloat162_rn(v1.x, v1.y);
        p[3] = __floats2bfloat162_rn(v1.z, v1.w);
        *(uint4*)(w2B + kk * 8192 + SWZ((uint32_t)(e * 128 + wi * 2))) = *(uint4*)p;
    }
    __syncthreads();

    {
        int r = tid & 127, chalf = tid >> 7;
        float mreg[24];
        #pragma unroll
        for (int f = 0; f < 24; f++) mreg[f] = msm[r * 25 + f];
        char* pan = h1B + chalf * 16384;
        #pragma unroll 4
        for (int c = 0; c < 64; c += 2) {
            int cc = chalf * 64 + c;
            float a0 = b1s[cc], a1 = b1s[cc + 1];
            const float* w0 = w1s + cc * 25;
            #pragma unroll
            for (int f = 0; f < 24; f++) {
                a0 += mreg[f] * w0[f];
                a1 += mreg[f] * w0[25 + f];
            }
            __nv_bfloat162 p = __floats2bfloat162_rn(fmaxf(a0, 0.f), fmaxf(a1, 0.f));
            *(__nv_bfloat162*)(pan + SWZ((uint32_t)(r * 128 + c * 2))) = p;
        }
    }
    __syncthreads();

    {
        int w = tid >> 5;
        int wm = (w & 1) * 64, wn = (w >> 1) * 16;
        uint32_t h1b = smem_u32(h1B);
        uint32_t w2b = smem_u32(w2B);
        float d[4][2][4] = {};
        #pragma unroll
        for (int kk = 0; kk < 2; kk++) {
            uint32_t ab = h1b + kk * 16384;
            uint32_t bb = w2b + kk * 8192;
            #pragma unroll
            for (int ks = 0; ks < 4; ks++) {
                uint32_t bfr[2][2];
                {
                    uint32_t by = (uint32_t)((wn + (lane & 15)) * 128 + (lane >> 4) * 16 + ks * 32);
                    uint32_t r0, r1, r2, r3;
                    LDSM_X4(r0, r1, r2, r3, bb + SWZ(by));
                    bfr[0][0] = r0; bfr[0][1] = r2;
                    bfr[1][0] = r1; bfr[1][1] = r3;
                }
                #pragma unroll
                for (int mt = 0; mt < 4; mt++) {
                    uint32_t a[4];
                    uint32_t by = (uint32_t)((wm + mt * 16 + (lane & 15)) * 128
                                             + (lane >> 4) * 16 + ks * 32);
                    LDSM_X4(a[0], a[1], a[2], a[3], ab + SWZ(by));
                    MMA16816(d[mt][0], a, bfr[0]);
                    MMA16816(d[mt][1], a, bfr[1]);
                }
            }
        }
        #pragma unroll
        for (int mt = 0; mt < 4; mt++)
            #pragma unroll
            for (int half = 0; half < 2; half++) {
                int row = bm + wm + mt * 16 + half * 8 + (lane >> 2);
                #pragma unroll
                for (int nt = 0; nt < 2; nt++) {
                    int e = wn + nt * 8 + (lane & 3) * 2;
                    *(float2*)&outp[(size_t)row * 256 + h * 64 + e] =
                        make_float2(d[mt][nt][half * 2], d[mt][nt][half * 2 + 1]);
                }
            }

        // ---- te/ta for mlp==0 (q in d registers) ----
        if (mlp == 0) {
            __syncthreads();   // all warps done reading h1B
            char* qB = h1B;    // reuse: [128][64] bf16 SW128
            #pragma unroll
            for (int mt = 0; mt < 4; mt++)
                #pragma unroll
                for (int half = 0; half < 2; half++) {
                    int rl = wm + mt * 16 + half * 8 + (lane >> 2);
                    #pragma unroll
                    for (int nt = 0; nt < 2; nt++) {
                        int e = wn + nt * 8 + (lane & 3) * 2;
                        *(__nv_bfloat162*)(qB + SWZ((uint32_t)(rl * 128 + e * 2))) =
                            __floats2bfloat162_rn(d[mt][nt][half * 2], d[mt][nt][half * 2 + 1]);
                    }
                }
            // Wk tile [32][64]: rows 0-15 = Wke (d), rows 16-31 = Wka
            for (int i = tid; i < 2048; i += 256) {
                int row = i >> 6, e = i & 63;
                int dd = row & 15;
                const float* Wk = (row < 16) ? Wke : Wka;
                *(__nv_bfloat16*)(w2B + SWZ((uint32_t)(row * 128 + e * 2))) =
                    __float2bfloat16_rn(Wk[h * 1024 + e * 16 + dd]);
            }
            __syncthreads();
            // mma: M=128 (batches), N=32 (te|ta), K=64
            int wm2 = w * 16;
            uint32_t ab2 = smem_u32(qB);
            uint32_t bb3 = smem_u32(w2B);
            float dd[4][4] = {};
            #pragma unroll
            for (int ks = 0; ks < 4; ks++) {
                uint32_t a[4];
                uint32_t by = (uint32_t)((wm2 + (lane & 15)) * 128 + (lane >> 4) * 16 + ks * 32);
                LDSM_X4(a[0], a[1], a[2], a[3], ab2 + SWZ(by));
                uint32_t bfr[4][2];
                #pragma unroll
                for (int nr = 0; nr < 2; nr++) {
                    uint32_t by2 = (uint32_t)((nr * 16 + (lane & 15)) * 128
                                              + (lane >> 4) * 16 + ks * 32);
                    uint32_t r0, r1, r2, r3;
                    LDSM_X4(r0, r1, r2, r3, bb3 + SWZ(by2));
                    bfr[nr * 2][0] = r0; bfr[nr * 2][1] = r2;
                    bfr[nr * 2 + 1][0] = r1; bfr[nr * 2 + 1][1] = r3;
                }
                #pragma unroll
                for (int nt = 0; nt < 4; nt++) MMA16816(dd[nt], a, bfr[nt]);
            }
            #pragma unroll
            for (int half = 0; half < 2; half++) {
                int bglob = bm + wm2 + half * 8 + (lane >> 2);
                #pragma unroll
                for (int nt = 0; nt < 4; nt++) {
                    int n = nt * 8 + (lane & 3) * 2;
                    float v0 = dd[nt][half * 2] * 0.125f;
                    float v1 = dd[nt][half * 2 + 1] * 0.125f;
                    float* dst = (n < 16) ? (g_te + bglob * 64 + h * 16 + n)
                                          : (g_ta + bglob * 64 + h * 16 + (n - 16));
                    *(float2*)dst = make_float2(v0, v1);
                }
            }
        }
    }
}

// =====================================================================
// K4: fused attention: tv from g_te/g_ta, l0/b_term/w_head -> logits ->
//     softmax -> register-built A-fragments -> tensor mix -> g_Abf
// =====================================================================
__global__ __launch_bounds__(256) void k_attn(const float* __restrict__ obs,
                                              const float* __restrict__ Wb2,
                                              const float* __restrict__ bb2,
                                              const float* __restrict__ Wh2,
                                              const float* __restrict__ bh2) {
    __shared__ float ent[2048];        // padded (rows 127 zeros)
    __shared__ float lg[512];
    __shared__ float u[512];
    __shared__ float vms[256];
    __shared__ float tv[128];
    __shared__ float whl[8];
    __shared__ __align__(128) __nv_bfloat16 Wvs[128 * 64];

    int b = blockIdx.x, tid = threadIdx.x;
    char* WvsB = (char*)Wvs;

    const float* orow = obs + (size_t)b * IN;
    {
        const float4* src4 = (const float4*)(orow + 4);
        #pragma unroll
        for (int i = tid; i < 508; i += 256) ((float4*)ent)[i] = src4[i];
        if (tid < 16) ent[2032 + tid] = 0.f;
    }
    {
        const uint4* wsrc = (const uint4*)g_Wvbf;
        #pragma unroll
        for (int i = tid; i < 1024; i += 256) {
            int row = i >> 3, c = i & 7;
            *(uint4*)(WvsB + SWZ((uint32_t)(row * 128 + c * 16))) = wsrc[i];
        }
    }
    vms[tid] = g_vm[b * 256 + tid];

    // ---- tv load + l0 (warps 0-3); b_term/w_head (warps 4-7) ----
    if (tid < 128) {
        tv[tid] = ((tid < 64) ? g_te : g_ta)[b * 64 + (tid & 63)];
        int w = tid >> 5, lane = tid & 31;
        float t = g_q[b * 256 + w * 64 + lane]      * g_km[b * 256 + w * 64 + lane]
                + g_q[b * 256 + w * 64 + 32 + lane] * g_km[b * 256 + w * 64 + 32 + lane];
        #pragma unroll
        for (int o = 16; o; o >>= 1) t += __shfl_xor_sync(0xffffffffu, t, o);
        if (lane == 0) whl[4 + w] = t * 0.125f;
    } else {
        int w = (tid >> 5) - 4, lane = tid & 31;
        const float* hrow = g_hid + b * 192;
        if (w == 0) {
            float s = hrow[lane] * Wb2[lane] + hrow[32 + lane] * Wb2[32 + lane];
            #pragma unroll
            for (int o = 16; o; o >>= 1) s += __shfl_xor_sync(0xffffffffu, s, o);
            if (lane == 0) g_bt[b] = s + bb2[0];
        }
        int h = (w == 0) ? 3 : (w - 1);
        float t = 0.f;
        #pragma unroll
        for (int j = lane; j < 128; j += 32) t += hrow[64 + j] * Wh2[h * 128 + j];
        #pragma unroll
        for (int o = 16; o; o >>= 1) t += __shfl_xor_sync(0xffffffffu, t, o);
        if (lane == 0) whl[h] = fabsf(t + bh2[h]);
    }
    __syncthreads();

    // ---- logits
    for (int i = tid; i < 508; i += 256) {
        int h = i / 127, n = i - h * 127;
        const float* tp = tv + ((n < 64) ? 0 : 64) + h * 16;
        const float* ep = ent + n * 16;
        float s = 0.f;
        #pragma unroll
        for (int d = 0; d < 16; d++) s += ep[d] * tp[d];
        lg[h * 128 + 1 + n] = s;
    }
    if (tid < 4) lg[tid * 128] = whl[4 + tid];
    __syncthreads();

    // ---- softmax (scaled by w_head) -> u
    if (tid < 128) {
        int h = tid >> 5, lane = tid & 31;
        float v0[4], m0 = -3.4e38f;
        #pragma unroll
        for (int j = 0; j < 4; j++) { v0[j] = lg[h * 128 + lane + 32 * j]; m0 = fmaxf(m0, v0[j]); }
        #pragma unroll
        for (int o = 16; o; o >>= 1) m0 = fmaxf(m0, __shfl_xor_sync(0xffffffffu, m0, o));
        float ss = 0.f;
        #pragma unroll
        for (int j = 0; j < 4; j++) { v0[j] = expf(v0[j] - m0); ss += v0[j]; }
        #pragma unroll
        for (int o = 16; o; o >>= 1) ss += __shfl_xor_sync(0xffffffffu, ss, o);
        float sc = whl[h] / ss;
        #pragma unroll
        for (int j = 0; j < 4; j++) u[h * 128 + lane + 32 * j] = v0[j] * sc;
    }
    __syncthreads();

    __nv_bfloat16* arow = g_Abf + (size_t)b * KTOT;
    if (tid < 64) {
        float s = 0.f;
        #pragma unroll
        for (int h = 0; h < 4; h++) s += u[h * 128] * vms[h * 64 + tid];
        arow[tid] = __float2bfloat16_rn(s);
    }

    // ---- tensor-core mix: A-fragments built in registers
    {
        int w = tid >> 5, lane = tid & 31;
        int sel = w >> 2;
        int mbase = w * 16;
        int r = mbase + (lane >> 2);
        int c0 = (lane & 3) * 2;
        uint32_t wb = smem_u32(Wvs) + (uint32_t)sel * 8192u;

        float2 eA = *(float2*)&ent[r * 16 + c0];
        float2 eB = *(float2*)&ent[r * 16 + c0 + 8];
        float2 eC = *(float2*)&ent[(r + 8) * 16 + c0];
        float2 eD = *(float2*)&ent[(r + 8) * 16 + c0 + 8];

        float d[8][4] = {};
        #pragma unroll
        for (int ks = 0; ks < 4; ks++) {
            float ul = (r < 127)     ? u[ks * 128 + r + 1] : 0.f;
            float uh = (r + 8 < 127) ? u[ks * 128 + r + 9] : 0.f;
            uint32_t a[4];
            a[0] = packbf2(ul * eA.x, ul * eA.y);
            a[1] = packbf2(uh * eC.x, uh * eC.y);
            a[2] = packbf2(ul * eB.x, ul * eB.y);
            a[3] = packbf2(uh * eD.x, uh * eD.y);
            uint32_t bfr[8][2];
            #pragma unroll
            for (int nr = 0; nr < 4; nr++) {
                uint32_t byte2 = (uint32_t)((nr * 16 + (lane & 15)) * 128 + (lane >> 4) * 16 + ks * 32);
                uint32_t r0, r1, r2, r3;
                LDSM_X4(r0, r1, r2, r3, wb + SWZ(byte2));
                bfr[nr * 2 + 0][0] = r0; bfr[nr * 2 + 0][1] = r2;
                bfr[nr * 2 + 1][0] = r1; bfr[nr * 2 + 1][1] = r3;
            }
            #pragma unroll
            for (int nt = 0; nt < 8; nt++) MMA16816(d[nt], a, bfr[nt]);
        }
        #pragma unroll
        for (int half = 0; half < 2; half++) {
            int Arow = mbase + half * 8 + (lane >> 2);
            if (Arow < 127) {
                int na = Arow + 1;
                #pragma unroll
                for (int nt = 0; nt < 8; nt++) {
                    int e = nt * 8 + (lane & 3) * 2;
                    __nv_bfloat162 v;
                    v.x = __float2bfloat16_rn(d[nt][half * 2 + 0]);
                    v.y = __float2bfloat16_rn(d[nt][half * 2 + 1]);
                    *(__nv_bfloat162*)(arow + na * 64 + e) = v;
                }
            }
        }
    }
}

// =====================================================================
// K5: bf16 mma GEMM: out[4096,256] = Abf @ Wfbf^T + bt*S + bf
// =====================================================================
__global__ __launch_bounds__(256) void k_final_mma(const float* __restrict__ bfv,
                                                   float* __restrict__ out) {
    __shared__ __align__(128) char sm8[49152];
    const uint32_t sb = smem_u32(sm8);
    const int tid = threadIdx.x, lane = tid & 31, w = tid >> 5;
    const int bm = blockIdx.x * 64, bn = blockIdx.y * 128;
    const int wm = (w & 1) * 32, wn = (w >> 1) * 32;
    const uint32_t Aoff[2] = {0u, 8192u};
    const uint32_t Boff[2] = {16384u, 32768u};

    float d[2][4][4] = {};

    auto loadChunk = [&](int t, int buf) {
        const __nv_bfloat16* Asrc = g_Abf + (size_t)bm * KTOT + (size_t)t * 64;
        #pragma unroll
        for (int i = 0; i < 2; i++) {
            int idx = tid + 256 * i;
            int row = idx >> 3, c = idx & 7;
            cp16(sb + Aoff[buf] + SWZ((uint32_t)(row * 128 + c * 16)),
                 Asrc + (size_t)row * KTOT + c * 8);
        }
        const __nv_bfloat16* Bsrc = g_Wfbf + (size_t)bn * KTOT + (size_t)t * 64;
        #pragma unroll
        for (int i = 0; i < 4; i++) {
            int idx = tid + 256 * i;
            int row = idx >> 3, c = idx & 7;
            cp16(sb + Boff[buf] + SWZ((uint32_t)(row * 128 + c * 16)),
                 Bsrc + (size_t)row * KTOT + c * 8);
        }
        CP_COMMIT();
    };

    loadChunk(0, 0);
    for (int t = 0; t < 128; t++) {
        const int buf = t & 1;
        if (t + 1 < 128) { loadChunk(t + 1, buf ^ 1); CP_WAIT(1); }
        else             { CP_WAIT(0); }
        __syncthreads();

        const uint32_t abase = sb + Aoff[buf];
        const uint32_t bbase = sb + Boff[buf];
        #pragma unroll
        for (int ks = 0; ks < 4; ks++) {
            uint32_t a[2][4], b[4][2];
            #pragma unroll
            for (int mt = 0; mt < 2; mt++) {
                uint32_t byte = (uint32_t)((wm + mt * 16 + (lane & 15)) * 128
                                           + (lane >> 4) * 16 + ks * 32);
                LDSM_X4(a[mt][0], a[mt][1], a[mt][2], a[mt][3], abase + SWZ(byte));
            }
            #pragma unroll
            for (int nr = 0; nr < 2; nr++) {
                uint32_t byte = (uint32_t)((wn + nr * 16 + (lane & 15)) * 128
                                           + (lane >> 4) * 16 + ks * 32);
                uint32_t r0, r1, r2, r3;
                LDSM_X4(r0, r1, r2, r3, bbase + SWZ(byte));
                b[nr * 2 + 0][0] = r0; b[nr * 2 + 0][1] = r2;
                b[nr * 2 + 1][0] = r1; b[nr * 2 + 1][1] = r3;
            }
            #pragma unroll
            for (int mt = 0; mt < 2; mt++)
                #pragma unroll
                for (int nt = 0; nt < 4; nt++)
                    MMA16816(d[mt][nt], a[mt], b[nt]);
        }
        __syncthreads();
    }

    const int nbase = bn + wn + (lane & 3) * 2;
    #pragma unroll
    for (int mt = 0; mt < 2; mt++) {
        #pragma unroll
        for (int half = 0; half < 2; half++) {
            int row = bm + wm + mt * 16 + half * 8 + (lane >> 2);
            float btv = g_bt[row];
            #pragma unroll
            for (int nt = 0; nt < 4; nt++) {
                int col = nbase + nt * 8;
                float v0 = d[mt][nt][half * 2 + 0] + btv * g_S[col]     + bfv[col];
                float v1 = d[mt][nt][half * 2 + 1] + btv * g_S[col + 1] + bfv[col + 1];
                *(float2*)&out[(size_t)row * RNN + col] = make_float2(v0, v1);
            }
        }
    }
}

// =====================================================================
// launch
// =====================================================================
extern "C" void kernel_launch(void* const* d_in, const int* in_sizes, int n_in,
                              void* d_out, int out_size) {
    const float* obs  = (const float*)d_in[0];
    const float* Wq1  = (const float*)d_in[1];
    const float* bq1  = (const float*)d_in[2];
    const float* Wq2  = (const float*)d_in[3];
    const float* Wkm1 = (const float*)d_in[4];
    const float* bkm1 = (const float*)d_in[5];
    const float* Wkm2 = (const float*)d_in[6];
    const float* Wke  = (const float*)d_in[7];
    const float* Wka  = (const float*)d_in[8];
    const float* Wvm1 = (const float*)d_in[9];
    const float* bvm1 = (const float*)d_in[10];
    const float* Wvm2 = (const float*)d_in[11];
    const float* Wve  = (const float*)d_in[12];
    const float* Wva  = (const float*)d_in[13];
    const float* Wb1  = (const float*)d_in[14];
    const float* bb1  = (const float*)d_in[15];
    const float* Wb2  = (const float*)d_in[16];
    const float* bb2  = (const float*)d_in[17];
    const float* Wh1  = (const float*)d_in[18];
    const float* bh1  = (const float*)d_in[19];
    const float* Wh2  = (const float*)d_in[20];
    const float* bh2  = (const float*)d_in[21];
    const float* Wf   = (const float*)d_in[22];
    const float* bf   = (const float*)d_in[23];
    float* out = (float*)d_out;

    const int mlp_smem = 75264;
    cudaFuncSetAttribute(k_mlp, cudaFuncAttributeMaxDynamicSharedMemorySize, mlp_smem);

    k_prep<<<449, 256>>>(Wf, Wve, Wva, Wb1, Wh1);
    k_front_tc<<<dim3(64, 3), 256>>>(obs, bb1, bh1);
    k_mlp<<<dim3(32, 12), 256, mlp_smem>>>(obs, Wq1, bq1, Wq2, Wkm1, bkm1, Wkm2,
                                           Wvm1, bvm1, Wvm2, Wke, Wka);
    k_attn<<<4096, 256>>>(obs, Wb2, bb2, Wh2, bh2);
    k_final_mma<<<dim3(64, 2), 256>>>(bf, out);
}

// round 10
// speedup vs baseline: 1.0072x; 1.0072x over previous
#include <cuda_runtime.h>
#include <cuda_bf16.h>
#include <cstdint>
#include <cstddef>

// ---------------- problem dims ----------------
#define BS 4096
#define IN 2056
#define MF 24
#define H 4
#define HE 128
#define E 64
#define NA 128
#define RNN 256
#define KTOT 8192         // E*NA
#define KF 2080           // front K in uint32 (bf16x2 pairs), 65 chunks of 32

// ---------------- scratch (device globals; no allocs allowed) ----------------
__device__ float g_hid[BS * 192];
__device__ float g_bt[BS];
__device__ float g_q[BS * H * E];
__device__ float g_km[BS * H * E];
__device__ float g_vm[BS * H * E];
__device__ float g_te[BS * 64];    // (q @ Wke^T)/8, [b][h*16+d]
__device__ float g_ta[BS * 64];    // (q @ Wka^T)/8
__device__ float g_S[RNN];
__device__ __align__(16) __nv_bfloat16 g_Abf[(size_t)BS * KTOT];
__device__ __align__(16) __nv_bfloat16 g_Wfbf[(size_t)RNN * KTOT];
__device__ __align__(16) __nv_bfloat16 g_Wvbf[2 * 64 * 64];
__device__ __align__(16) uint32_t g_WB[(size_t)2 * 192 * KF];

// ---------------- PTX helpers ----------------
__device__ __forceinline__ uint32_t smem_u32(const void* p) {
    uint32_t a;
    asm("{ .reg .u64 t; cvta.to.shared.u64 t, %1; cvt.u32.u64 %0, t; }" : "=r"(a) : "l"(p));
    return a;
}
__device__ __forceinline__ void cp16(uint32_t dst, const void* src) {
    asm volatile("cp.async.cg.shared.global [%0], [%1], 16;" :: "r"(dst), "l"(src) : "memory");
}
#define CP_COMMIT() asm volatile("cp.async.commit_group;" ::: "memory")
#define CP_WAIT(n)  asm volatile("cp.async.wait_group %0;" :: "n"(n) : "memory")

#define LDSM_X4(r0, r1, r2, r3, addr) \
    asm volatile("ldmatrix.sync.aligned.m8n8.x4.shared.b16 {%0,%1,%2,%3}, [%4];" \
                 : "=r"(r0), "=r"(r1), "=r"(r2), "=r"(r3) : "r"(addr))

#define MMA16816(d, a, b) \
    asm volatile("mma.sync.aligned.m16n8k16.row.col.f32.bf16.bf16.f32 " \
                 "{%0,%1,%2,%3}, {%4,%5,%6,%7}, {%8,%9}, {%0,%1,%2,%3};" \
                 : "+f"((d)[0]), "+f"((d)[1]), "+f"((d)[2]), "+f"((d)[3]) \
                 : "r"((a)[0]), "r"((a)[1]), "r"((a)[2]), "r"((a)[3]), \
                   "r"((b)[0]), "r"((b)[1]))

#define SWZ(x) ((x) ^ (((x) >> 3) & 0x70))

__device__ __forceinline__ uint32_t packbf2(float x, float y) {
    __nv_bfloat162 p = __floats2bfloat162_rn(x, y);
    return *(uint32_t*)&p;
}
__device__ __forceinline__ float dot4(float4 a, float4 b) {
    return a.x * b.x + a.y * b.y + a.z * b.z + a.w * b.w;
}

// =====================================================================
// K0: prep
// =====================================================================
__global__ __launch_bounds__(256) void k_prep(const float* __restrict__ Wf,
                                              const float* __restrict__ Wve,
                                              const float* __restrict__ Wva,
                                              const float* __restrict__ Wb1,
                                              const float* __restrict__ Wh1) {
    int r = blockIdx.x;
    int tid = threadIdx.x;
    if (r < 256) {
        __shared__ float row[8256];
        __shared__ float red[8];
        float s = 0.f;
        for (int i = tid; i < 8192; i += 256) {
            float v = Wf[(size_t)r * 8192 + i];
            row[i + (i >> 7)] = v;
            s += v;
        }
        #pragma unroll
        for (int o = 16; o; o >>= 1) s += __shfl_xor_sync(0xffffffffu, s, o);
        if ((tid & 31) == 0) red[tid >> 5] = s;
        __syncthreads();
        if (tid == 0) {
            float t = 0.f;
            #pragma unroll
            for (int j = 0; j < 8; j++) t += red[j];
            g_S[r] = t;
        }
        for (int i = tid; i < 8192; i += 256) {
            int na = i >> 6, e = i & 63;
            int src = e * 128 + na;
            g_Wfbf[(size_t)r * 8192 + i] = __float2bfloat16_rn(row[src + (src >> 7)]);
        }
    } else if (r == 256) {
        for (int i = tid; i < 8192; i += 256) {
            int sel = i >> 12, j = i & 4095;
            int e = j >> 6, hd = j & 63, h = hd >> 4, d = hd & 15;
            const float* W = sel ? Wva : Wve;
            g_Wvbf[i] = __float2bfloat16_rn(W[h * 1024 + e * 16 + d]);
        }
    } else {
        int n = r - 257;
        const float* W = (n < 64) ? (Wb1 + (size_t)n * IN) : (Wh1 + (size_t)(n - 64) * IN);
        uint32_t* d0 = g_WB + (size_t)n * KF;
        uint32_t* d1 = g_WB + (size_t)192 * KF + (size_t)n * KF;
        for (int k = tid; k < IN; k += 256) {
            float x = W[k];
            __nv_bfloat16 hi = __float2bfloat16_rn(x);
            __nv_bfloat16 lo = __float2bfloat16_rn(x - __bfloat162float(hi));
            __nv_bfloat162 p0; p0.x = hi; p0.y = hi;
            __nv_bfloat162 p1; p1.x = lo; p1.y = lo;
            d0[k] = *(uint32_t*)&p0;
            d1[k] = *(uint32_t*)&p1;
        }
    }
}

// =====================================================================
// K1: front GEMM (split-bf16 exact, obs converted in-register)
// =====================================================================
__global__ __launch_bounds__(256) void k_front_tc(const float* __restrict__ obs,
                                                  const float* __restrict__ bb1,
                                                  const float* __restrict__ bh1) {
    __shared__ __align__(128) char sm8[49152];
    const uint32_t sb = smem_u32(sm8);
    const int tid = threadIdx.x, lane = tid & 31, w = tid >> 5;
    const int bm = blockIdx.x * 64, bn = blockIdx.y * 64;
    const int wm = (w & 3) * 16, wn = (w >> 2) * 32;
    float d[4][4] = {};

    auto stageA = [&](int t, int buf) {
        #pragma unroll
        for (int i = 0; i < 2; i++) {
            int idx = tid + 256 * i;
            int row = idx >> 3, c16 = idx & 7;
            int k0 = t * 32 + c16 * 4;
            float4 v = make_float4(0.f, 0.f, 0.f, 0.f);
            if (k0 < IN) v = *(const float4*)(obs + (size_t)(bm + row) * IN + k0);
            uint32_t p[4];
            {
                float xs[4] = {v.x, v.y, v.z, v.w};
                #pragma unroll
                for (int j = 0; j < 4; j++) {
                    __nv_bfloat16 hi = __float2bfloat16_rn(xs[j]);
                    __nv_bfloat16 lo = __float2bfloat16_rn(xs[j] - __bfloat162float(hi));
                    __nv_bfloat162 pr; pr.x = hi; pr.y = lo;
                    p[j] = *(uint32_t*)&pr;
                }
            }
            *(uint4*)(sm8 + buf * 8192 + SWZ((uint32_t)(row * 128 + c16 * 16))) = *(uint4*)p;
        }
    };
    auto stageB = [&](int t, int buf) {
        #pragma unroll
        for (int i = 0; i < 2; i++) {
            int idx = tid + 256 * i;
            int row = idx >> 3, c16 = idx & 7;
            const uint32_t* s0 = g_WB + (size_t)(bn + row) * KF + t * 32 + c16 * 4;
            uint32_t off = SWZ((uint32_t)(row * 128 + c16 * 16));
            cp16(sb + 16384 + buf * 8192 + off, s0);
            cp16(sb + 32768 + buf * 8192 + off, s0 + (size_t)192 * KF);
        }
        CP_COMMIT();
    };

    stageA(0, 0);
    stageB(0, 0);
    for (int t = 0; t < 65; t++) {
        const int buf = t & 1;
        if (t < 64) {
            stageA(t + 1, buf ^ 1);
            stageB(t + 1, buf ^ 1);
            CP_WAIT(1);
        } else {
            CP_WAIT(0);
        }
        __syncthreads();
        const uint32_t ab = sb + buf * 8192;
        const uint32_t b0b = sb + 16384 + buf * 8192;
        const uint32_t b1b = sb + 32768 + buf * 8192;
        #pragma unroll
        for (int ks = 0; ks < 4; ks++) {
            uint32_t a[4];
            uint32_t byte = (uint32_t)((wm + (lane & 15)) * 128 + (lane >> 4) * 16 + ks * 32);
            LDSM_X4(a[0], a[1], a[2], a[3], ab + SWZ(byte));
            uint32_t b0[4][2], b1[4][2];
            #pragma unroll
            for (int nr = 0; nr < 2; nr++) {
                uint32_t by2 = (uint32_t)((wn + nr * 16 + (lane & 15)) * 128
                                          + (lane >> 4) * 16 + ks * 32);
                uint32_t r0, r1, r2, r3;
                LDSM_X4(r0, r1, r2, r3, b0b + SWZ(by2));
                b0[nr * 2][0] = r0; b0[nr * 2][1] = r2;
                b0[nr * 2 + 1][0] = r1; b0[nr * 2 + 1][1] = r3;
                LDSM_X4(r0, r1, r2, r3, b1b + SWZ(by2));
                b1[nr * 2][0] = r0; b1[nr * 2][1] = r2;
                b1[nr * 2 + 1][0] = r1; b1[nr * 2 + 1][1] = r3;
            }
            #pragma unroll
            for (int nt = 0; nt < 4; nt++) {
                MMA16816(d[nt], a, b0[nt]);
                MMA16816(d[nt], a, b1[nt]);
            }
        }
        __syncthreads();
    }

    #pragma unroll
    for (int half = 0; half < 2; half++) {
        int row = bm + wm + half * 8 + (lane >> 2);
        #pragma unroll
        for (int nt = 0; nt < 4; nt++) {
            int n = bn + wn + nt * 8 + (lane & 3) * 2;
            float bias0 = (n < 64) ? bb1[n] : bh1[n - 64];
            float bias1 = (n + 1 < 64) ? bb1[n + 1] : bh1[n + 1 - 64];
            float v0 = fmaxf(d[nt][half * 2 + 0] + bias0, 0.f);
            float v1 = fmaxf(d[nt][half * 2 + 1] + bias1, 0.f);
            *(float2*)&g_hid[row * 192 + n] = make_float2(v0, v1);
        }
    }
}

// =====================================================================
// K3: fused m-MLPs; mlp==0 also computes te/ta via mma
// =====================================================================
__global__ __launch_bounds__(256) void k_mlp(const float* __restrict__ obs,
                                             const float* __restrict__ Wq1, const float* __restrict__ bq1,
                                             const float* __restrict__ Wq2,
                                             const float* __restrict__ Wkm1, const float* __restrict__ bkm1,
                                             const float* __restrict__ Wkm2,
                                             const float* __restrict__ Wvm1, const float* __restrict__ bvm1,
                                             const float* __restrict__ Wvm2,
                                             const float* __restrict__ Wke,
                                             const float* __restrict__ Wka) {
    extern __shared__ __align__(128) char smp[];
    float* msm = (float*)smp;
    float* w1s = (float*)(smp + 12800);
    float* b1s = (float*)(smp + 25600);
    char* h1B = smp + 26112;
    char* w2B = smp + 58880;

    const int tid = threadIdx.x, lane = tid & 31;
    const int bm = blockIdx.x * 128;
    const int mlp = blockIdx.y >> 2, h = blockIdx.y & 3;
    const float* W1 = ((mlp == 0) ? Wq1 : (mlp == 1) ? Wkm1 : Wvm1) + h * HE * MF;
    const float* B1 = ((mlp == 0) ? bq1 : (mlp == 1) ? bkm1 : bvm1) + h * HE;
    const float* W2 = ((mlp == 0) ? Wq2 : (mlp == 1) ? Wkm2 : Wvm2) + h * E * HE;
    float* outp = (mlp == 0) ? g_q : (mlp == 1) ? g_km : g_vm;

    for (int i = tid; i < 128 * 24; i += 256) {
        int r = i / 24, f = i - r * 24;
        int col = (f < 4) ? f : (2032 + f);
        msm[r * 25 + f] = obs[(size_t)(bm + r) * IN + col];
    }
    for (int i = tid; i < 128 * 24; i += 256) {
        int g = i / 24, f = i - g * 24;
        w1s[g * 25 + f] = W1[g * 24 + f];
    }
    if (tid < 128) b1s[tid] = B1[tid];
    for (int i = tid; i < 1024; i += 256) {
        int e = i >> 4, g8 = (i & 15) * 8;
        int kk = g8 >> 6, wi = g8 & 63;
        const float* src = W2 + e * HE + g8;
        float4 v0 = *(const float4*)src;
        float4 v1 = *(const float4*)(src + 4);
        __nv_bfloat162 p[4];
        p[0] = __floats2bfloat162_rn(v0.x, v0.y);
        p[1] = __floats2bfloat162_rn(v0.z, v0.w);
        p[2] = __floats2bfloat162_rn(v1.x, v1.y);
        p[3] = __floats2bfloat162_rn(v1.z, v1.w);
        *(uint4*)(w2B + kk * 8192 + SWZ((uint32_t)(e * 128 + wi * 2))) = *(uint4*)p;
    }
    __syncthreads();

    {
        int r = tid & 127, chalf = tid >> 7;
        float mreg[24];
        #pragma unroll
        for (int f = 0; f < 24; f++) mreg[f] = msm[r * 25 + f];
        char* pan = h1B + chalf * 16384;
        #pragma unroll 4
        for (int c = 0; c < 64; c += 2) {
            int cc = chalf * 64 + c;
            float a0 = b1s[cc], a1 = b1s[cc + 1];
            const float* w0 = w1s + cc * 25;
            #pragma unroll
            for (int f = 0; f < 24; f++) {
                a0 += mreg[f] * w0[f];
                a1 += mreg[f] * w0[25 + f];
            }
            __nv_bfloat162 p = __floats2bfloat162_rn(fmaxf(a0, 0.f), fmaxf(a1, 0.f));
            *(__nv_bfloat162*)(pan + SWZ((uint32_t)(r * 128 + c * 2))) = p;
        }
    }
    __syncthreads();

    {
        int w = tid >> 5;
        int wm = (w & 1) * 64, wn = (w >> 1) * 16;
        uint32_t h1b = smem_u32(h1B);
        uint32_t w2b = smem_u32(w2B);
        float d[4][2][4] = {};
        #pragma unroll
        for (int kk = 0; kk < 2; kk++) {
            uint32_t ab = h1b + kk * 16384;
            uint32_t bb = w2b + kk * 8192;
            #pragma unroll
            for (int ks = 0; ks < 4; ks++) {
                uint32_t bfr[2][2];
                {
                    uint32_t by = (uint32_t)((wn + (lane & 15)) * 128 + (lane >> 4) * 16 + ks * 32);
                    uint32_t r0, r1, r2, r3;
                    LDSM_X4(r0, r1, r2, r3, bb + SWZ(by));
                    bfr[0][0] = r0; bfr[0][1] = r2;
                    bfr[1][0] = r1; bfr[1][1] = r3;
                }
                #pragma unroll
                for (int mt = 0; mt < 4; mt++) {
                    uint32_t a[4];
                    uint32_t by = (uint32_t)((wm + mt * 16 + (lane & 15)) * 128
                                             + (lane >> 4) * 16 + ks * 32);
                    LDSM_X4(a[0], a[1], a[2], a[3], ab + SWZ(by));
                    MMA16816(d[mt][0], a, bfr[0]);
                    MMA16816(d[mt][1], a, bfr[1]);
                }
            }
        }
        #pragma unroll
        for (int mt = 0; mt < 4; mt++)
            #pragma unroll
            for (int half = 0; half < 2; half++) {
                int row = bm + wm + mt * 16 + half * 8 + (lane >> 2);
                #pragma unroll
                for (int nt = 0; nt < 2; nt++) {
                    int e = wn + nt * 8 + (lane & 3) * 2;
                    *(float2*)&outp[(size_t)row * 256 + h * 64 + e] =
                        make_float2(d[mt][nt][half * 2], d[mt][nt][half * 2 + 1]);
                }
            }

        if (mlp == 0) {
            __syncthreads();
            char* qB = h1B;
            #pragma unroll
            for (int mt = 0; mt < 4; mt++)
                #pragma unroll
                for (int half = 0; half < 2; half++) {
                    int rl = wm + mt * 16 + half * 8 + (lane >> 2);
                    #pragma unroll
                    for (int nt = 0; nt < 2; nt++) {
                        int e = wn + nt * 8 + (lane & 3) * 2;
                        *(__nv_bfloat162*)(qB + SWZ((uint32_t)(rl * 128 + e * 2))) =
                            __floats2bfloat162_rn(d[mt][nt][half * 2], d[mt][nt][half * 2 + 1]);
                    }
                }
            for (int i = tid; i < 2048; i += 256) {
                int row = i >> 6, e = i & 63;
                int dd = row & 15;
                const float* Wk = (row < 16) ? Wke : Wka;
                *(__nv_bfloat16*)(w2B + SWZ((uint32_t)(row * 128 + e * 2))) =
                    __float2bfloat16_rn(Wk[h * 1024 + e * 16 + dd]);
            }
            __syncthreads();
            int wm2 = w * 16;
            uint32_t ab2 = smem_u32(qB);
            uint32_t bb3 = smem_u32(w2B);
            float dd[4][4] = {};
            #pragma unroll
            for (int ks = 0; ks < 4; ks++) {
                uint32_t a[4];
                uint32_t by = (uint32_t)((wm2 + (lane & 15)) * 128 + (lane >> 4) * 16 + ks * 32);
                LDSM_X4(a[0], a[1], a[2], a[3], ab2 + SWZ(by));
                uint32_t bfr[4][2];
                #pragma unroll
                for (int nr = 0; nr < 2; nr++) {
                    uint32_t by2 = (uint32_t)((nr * 16 + (lane & 15)) * 128
                                              + (lane >> 4) * 16 + ks * 32);
                    uint32_t r0, r1, r2, r3;
                    LDSM_X4(r0, r1, r2, r3, bb3 + SWZ(by2));
                    bfr[nr * 2][0] = r0; bfr[nr * 2][1] = r2;
                    bfr[nr * 2 + 1][0] = r1; bfr[nr * 2 + 1][1] = r3;
                }
                #pragma unroll
                for (int nt = 0; nt < 4; nt++) MMA16816(dd[nt], a, bfr[nt]);
            }
            #pragma unroll
            for (int half = 0; half < 2; half++) {
                int bglob = bm + wm2 + half * 8 + (lane >> 2);
                #pragma unroll
                for (int nt = 0; nt < 4; nt++) {
                    int n = nt * 8 + (lane & 3) * 2;
                    float v0 = dd[nt][half * 2] * 0.125f;
                    float v1 = dd[nt][half * 2 + 1] * 0.125f;
                    float* dst = (n < 16) ? (g_te + bglob * 64 + h * 16 + n)
                                          : (g_ta + bglob * 64 + h * 16 + (n - 16));
                    *(float2*)dst = make_float2(v0, v1);
                }
            }
        }
    }
}

// =====================================================================
// K4: attention, 2 batches per CTA. Wv staged once; B-fragments reused
// across both batches; vectorized logits; in-place softmax on u.
// =====================================================================
__global__ __launch_bounds__(256, 2) void k_attn(const float* __restrict__ obs,
                                                 const float* __restrict__ Wb2,
                                                 const float* __restrict__ bb2,
                                                 const float* __restrict__ Wh2,
                                                 const float* __restrict__ bh2) {
    __shared__ float ent2[2 * 2048];
    __shared__ float u2[2 * 512];
    __shared__ float vms2[2 * 256];
    __shared__ float tv2[2 * 128];
    __shared__ float whl2[2 * 8];
    __shared__ __align__(128) __nv_bfloat16 Wvs[128 * 64];

    const int tid = threadIdx.x;
    const int b0 = blockIdx.x * 2;
    const int lt = tid & 127, jb = tid >> 7;   // per-batch thread split
    char* WvsB = (char*)Wvs;

    // ---- stage: ent for both batches (each half loads its batch)
    {
        const float4* src4 = (const float4*)(obs + (size_t)(b0 + jb) * IN + 4);
        float4* dst4 = (float4*)(ent2 + jb * 2048);
        #pragma unroll
        for (int i = lt; i < 508; i += 128) dst4[i] = src4[i];
        if (lt < 16) ent2[jb * 2048 + 2032 + lt] = 0.f;
    }
    // Wv (16 KB) once
    {
        const uint4* wsrc = (const uint4*)g_Wvbf;
        #pragma unroll
        for (int i = tid; i < 1024; i += 256) {
            int row = i >> 3, c = i & 7;
            *(uint4*)(WvsB + SWZ((uint32_t)(row * 128 + c * 16))) = wsrc[i];
        }
    }
    // vms both batches
    vms2[jb * 256 + lt] = g_vm[(b0 + jb) * 256 + lt];
    vms2[jb * 256 + ((lt + 128) & 255)] = g_vm[(b0 + jb) * 256 + ((lt + 128) & 255)];

    // ---- fold: tv + l0 + b_term + w_head, 128 threads per batch
    {
        int b = b0 + jb;
        tv2[jb * 128 + lt] = ((lt < 64) ? g_te : g_ta)[b * 64 + (lt & 63)];
        int wl = lt >> 5, lane = lt & 31;
        // l0 for head wl
        float t = g_q[b * 256 + wl * 64 + lane]      * g_km[b * 256 + wl * 64 + lane]
                + g_q[b * 256 + wl * 64 + 32 + lane] * g_km[b * 256 + wl * 64 + 32 + lane];
        #pragma unroll
        for (int o = 16; o; o >>= 1) t += __shfl_xor_sync(0xffffffffu, t, o);
        if (lane == 0) whl2[jb * 8 + 4 + wl] = t * 0.125f;
        // w_head for head wl
        const float* hrow = g_hid + b * 192;
        float s = 0.f;
        #pragma unroll
        for (int j = lane; j < 128; j += 32) s += hrow[64 + j] * Wh2[wl * 128 + j];
        #pragma unroll
        for (int o = 16; o; o >>= 1) s += __shfl_xor_sync(0xffffffffu, s, o);
        if (lane == 0) whl2[jb * 8 + wl] = fabsf(s + bh2[wl]);
        // b_term (warp 0 of each half)
        if (wl == 0) {
            float bsum = hrow[lane] * Wb2[lane] + hrow[32 + lane] * Wb2[32 + lane];
            #pragma unroll
            for (int o = 16; o; o >>= 1) bsum += __shfl_xor_sync(0xffffffffu, bsum, o);
            if (lane == 0) g_bt[b] = bsum + bb2[0];
        }
    }
    __syncthreads();

    // ---- logits (vectorized) -> u2
    {
        const float* ent = ent2 + jb * 2048;
        const float* tv = tv2 + jb * 128;
        float* u = u2 + jb * 512;
        #pragma unroll
        for (int i = lt; i < 508; i += 128) {
            int h = i / 127, n = i - h * 127;
            const float4* tp = (const float4*)(tv + ((n < 64) ? 0 : 64) + h * 16);
            const float4* ep = (const float4*)(ent + n * 16);
            float s = dot4(ep[0], tp[0]) + dot4(ep[1], tp[1])
                    + dot4(ep[2], tp[2]) + dot4(ep[3], tp[3]);
            u[h * 128 + 1 + n] = s;
        }
        if (lt < 4) u[lt * 128] = whl2[jb * 8 + 4 + lt];
    }
    __syncthreads();

    // ---- softmax in-place on u2 (128 threads per batch)
    {
        float* u = u2 + jb * 512;
        int h = lt >> 5, lane = lt & 31;
        float v0[4], m0 = -3.4e38f;
        #pragma unroll
        for (int j = 0; j < 4; j++) { v0[j] = u[h * 128 + lane + 32 * j]; m0 = fmaxf(m0, v0[j]); }
        #pragma unroll
        for (int o = 16; o; o >>= 1) m0 = fmaxf(m0, __shfl_xor_sync(0xffffffffu, m0, o));
        float ss = 0.f;
        #pragma unroll
        for (int j = 0; j < 4; j++) { v0[j] = expf(v0[j] - m0); ss += v0[j]; }
        #pragma unroll
        for (int o = 16; o; o >>= 1) ss += __shfl_xor_sync(0xffffffffu, ss, o);
        float sc = whl2[jb * 8 + h] / ss;
        #pragma unroll
        for (int j = 0; j < 4; j++) u[h * 128 + lane + 32 * j] = v0[j] * sc;
    }
    __syncthreads();

    // ---- na=0 rows for both batches
    if (lt < 64) {
        const float* u = u2 + jb * 512;
        const float* vms = vms2 + jb * 256;
        float s = 0.f;
        #pragma unroll
        for (int h = 0; h < 4; h++) s += u[h * 128] * vms[h * 64 + lt];
        g_Abf[(size_t)(b0 + jb) * KTOT + lt] = __float2bfloat16_rn(s);
    }

    // ---- tensor-core mix, both batches share B-fragments
    {
        int w = tid >> 5, lane = tid & 31;
        int sel = w >> 2;
        int mbase = w * 16;
        int r = mbase + (lane >> 2);
        int c0 = (lane & 3) * 2;
        uint32_t wb = smem_u32(Wvs) + (uint32_t)sel * 8192u;

        float2 eA[2], eB[2], eC[2], eD[2];
        #pragma unroll
        for (int j = 0; j < 2; j++) {
            const float* ent = ent2 + j * 2048;
            eA[j] = *(float2*)&ent[r * 16 + c0];
            eB[j] = *(float2*)&ent[r * 16 + c0 + 8];
            eC[j] = *(float2*)&ent[(r + 8) * 16 + c0];
            eD[j] = *(float2*)&ent[(r + 8) * 16 + c0 + 8];
        }

        float d[2][8][4] = {};
        #pragma unroll
        for (int ks = 0; ks < 4; ks++) {
            uint32_t bfr[8][2];
            #pragma unroll
            for (int nr = 0; nr < 4; nr++) {
                uint32_t byte2 = (uint32_t)((nr * 16 + (lane & 15)) * 128 + (lane >> 4) * 16 + ks * 32);
                uint32_t r0, r1, r2, r3;
                LDSM_X4(r0, r1, r2, r3, wb + SWZ(byte2));
                bfr[nr * 2 + 0][0] = r0; bfr[nr * 2 + 0][1] = r2;
                bfr[nr * 2 + 1][0] = r1; bfr[nr * 2 + 1][1] = r3;
            }
            #pragma unroll
            for (int j = 0; j < 2; j++) {
                const float* u = u2 + j * 512;
                float ul = (r < 127)     ? u[ks * 128 + r + 1] : 0.f;
                float uh = (r + 8 < 127) ? u[ks * 128 + r + 9] : 0.f;
                uint32_t a[4];
                a[0] = packbf2(ul * eA[j].x, ul * eA[j].y);
                a[1] = packbf2(uh * eC[j].x, uh * eC[j].y);
                a[2] = packbf2(ul * eB[j].x, ul * eB[j].y);
                a[3] = packbf2(uh * eD[j].x, uh * eD[j].y);
                #pragma unroll
                for (int nt = 0; nt < 8; nt++) MMA16816(d[j][nt], a, bfr[nt]);
            }
        }
        #pragma unroll
        for (int j = 0; j < 2; j++) {
            __nv_bfloat16* arow = g_Abf + (size_t)(b0 + j) * KTOT;
            #pragma unroll
            for (int half = 0; half < 2; half++) {
                int Arow = mbase + half * 8 + (lane >> 2);
                if (Arow < 127) {
                    int na = Arow + 1;
                    #pragma unroll
                    for (int nt = 0; nt < 8; nt++) {
                        int e = nt * 8 + (lane & 3) * 2;
                        __nv_bfloat162 v;
                        v.x = __float2bfloat16_rn(d[j][nt][half * 2 + 0]);
                        v.y = __float2bfloat16_rn(d[j][nt][half * 2 + 1]);
                        *(__nv_bfloat162*)(arow + na * 64 + e) = v;
                    }
                }
            }
        }
    }
}

// =====================================================================
// K5: bf16 mma GEMM: out[4096,256] = Abf @ Wfbf^T + bt*S + bf
// =====================================================================
__global__ __launch_bounds__(256) void k_final_mma(const float* __restrict__ bfv,
                                                   float* __restrict__ out) {
    __shared__ __align__(128) char sm8[49152];
    const uint32_t sb = smem_u32(sm8);
    const int tid = threadIdx.x, lane = tid & 31, w = tid >> 5;
    const int bm = blockIdx.x * 64, bn = blockIdx.y * 128;
    const int wm = (w & 1) * 32, wn = (w >> 1) * 32;
    const uint32_t Aoff[2] = {0u, 8192u};
    const uint32_t Boff[2] = {16384u, 32768u};

    float d[2][4][4] = {};

    auto loadChunk = [&](int t, int buf) {
        const __nv_bfloat16* Asrc = g_Abf + (size_t)bm * KTOT + (size_t)t * 64;
        #pragma unroll
        for (int i = 0; i < 2; i++) {
            int idx = tid + 256 * i;
            int row = idx >> 3, c = idx & 7;
            cp16(sb + Aoff[buf] + SWZ((uint32_t)(row * 128 + c * 16)),
                 Asrc + (size_t)row * KTOT + c * 8);
        }
        const __nv_bfloat16* Bsrc = g_Wfbf + (size_t)bn * KTOT + (size_t)t * 64;
        #pragma unroll
        for (int i = 0; i < 4; i++) {
            int idx = tid + 256 * i;
            int row = idx >> 3, c = idx & 7;
            cp16(sb + Boff[buf] + SWZ((uint32_t)(row * 128 + c * 16)),
                 Bsrc + (size_t)row * KTOT + c * 8);
        }
        CP_COMMIT();
    };

    loadChunk(0, 0);
    for (int t = 0; t < 128; t++) {
        const int buf = t & 1;
        if (t + 1 < 128) { loadChunk(t + 1, buf ^ 1); CP_WAIT(1); }
        else             { CP_WAIT(0); }
        __syncthreads();

        const uint32_t abase = sb + Aoff[buf];
        const uint32_t bbase = sb + Boff[buf];
        #pragma unroll
        for (int ks = 0; ks < 4; ks++) {
            uint32_t a[2][4], b[4][2];
            #pragma unroll
            for (int mt = 0; mt < 2; mt++) {
                uint32_t byte = (uint32_t)((wm + mt * 16 + (lane & 15)) * 128
                                           + (lane >> 4) * 16 + ks * 32);
                LDSM_X4(a[mt][0], a[mt][1], a[mt][2], a[mt][3], abase + SWZ(byte));
            }
            #pragma unroll
            for (int nr = 0; nr < 2; nr++) {
                uint32_t byte = (uint32_t)((wn + nr * 16 + (lane & 15)) * 128
                                           + (lane >> 4) * 16 + ks * 32);
                uint32_t r0, r1, r2, r3;
                LDSM_X4(r0, r1, r2, r3, bbase + SWZ(byte));
                b[nr * 2 + 0][0] = r0; b[nr * 2 + 0][1] = r2;
                b[nr * 2 + 1][0] = r1; b[nr * 2 + 1][1] = r3;
            }
            #pragma unroll
            for (int mt = 0; mt < 2; mt++)
                #pragma unroll
                for (int nt = 0; nt < 4; nt++)
                    MMA16816(d[mt][nt], a[mt], b[nt]);
        }
        __syncthreads();
    }

    const int nbase = bn + wn + (lane & 3) * 2;
    #pragma unroll
    for (int mt = 0; mt < 2; mt++) {
        #pragma unroll
        for (int half = 0; half < 2; half++) {
            int row = bm + wm + mt * 16 + half * 8 + (lane >> 2);
            float btv = g_bt[row];
            #pragma unroll
            for (int nt = 0; nt < 4; nt++) {
                int col = nbase + nt * 8;
                float v0 = d[mt][nt][half * 2 + 0] + btv * g_S[col]     + bfv[col];
                float v1 = d[mt][nt][half * 2 + 1] + btv * g_S[col + 1] + bfv[col + 1];
                *(float2*)&out[(size_t)row * RNN + col] = make_float2(v0, v1);
            }
        }
    }
}

// =====================================================================
// launch
// =====================================================================
extern "C" void kernel_launch(void* const* d_in, const int* in_sizes, int n_in,
                              void* d_out, int out_size) {
    const float* obs  = (const float*)d_in[0];
    const float* Wq1  = (const float*)d_in[1];
    const float* bq1  = (const float*)d_in[2];
    const float* Wq2  = (const float*)d_in[3];
    const float* Wkm1 = (const float*)d_in[4];
    const float* bkm1 = (const float*)d_in[5];
    const float* Wkm2 = (const float*)d_in[6];
    const float* Wke  = (const float*)d_in[7];
    const float* Wka  = (const float*)d_in[8];
    const float* Wvm1 = (const float*)d_in[9];
    const float* bvm1 = (const float*)d_in[10];
    const float* Wvm2 = (const float*)d_in[11];
    const float* Wve  = (const float*)d_in[12];
    const float* Wva  = (const float*)d_in[13];
    const float* Wb1  = (const float*)d_in[14];
    const float* bb1  = (const float*)d_in[15];
    const float* Wb2  = (const float*)d_in[16];
    const float* bb2  = (const float*)d_in[17];
    const float* Wh1  = (const float*)d_in[18];
    const float* bh1  = (const float*)d_in[19];
    const float* Wh2  = (const float*)d_in[20];
    const float* bh2  = (const float*)d_in[21];
    const float* Wf   = (const float*)d_in[22];
    const float* bf   = (const float*)d_in[23];
    float* out = (float*)d_out;

    const int mlp_smem = 75264;
    cudaFuncSetAttribute(k_mlp, cudaFuncAttributeMaxDynamicSharedMemorySize, mlp_smem);

    k_prep<<<449, 256>>>(Wf, Wve, Wva, Wb1, Wh1);
    k_front_tc<<<dim3(64, 3), 256>>>(obs, bb1, bh1);
    k_mlp<<<dim3(32, 12), 256, mlp_smem>>>(obs, Wq1, bq1, Wq2, Wkm1, bkm1, Wkm2,
                                           Wvm1, bvm1, Wvm2, Wke, Wka);
    k_attn<<<2048, 256>>>(obs, Wb2, bb2, Wh2, bh2);
    k_final_mma<<<dim3(64, 2), 256>>>(bf, out);
}

// round 11
// speedup vs baseline: 1.1515x; 1.1433x over previous
#include <cuda_runtime.h>
#include <cuda_bf16.h>
#include <cstdint>
#include <cstddef>

// ---------------- problem dims ----------------
#define BS 4096
#define IN 2056
#define MF 24
#define H 4
#define HE 128
#define E 64
#define NA 128
#define RNN 256
#define KTOT 8192         // E*NA
#define KF 2080           // front K in uint32 (bf16x2 pairs), 65 chunks of 32

// ---------------- scratch (device globals; no allocs allowed) ----------------
__device__ float g_hid[BS * 192];
__device__ float g_bt[BS];
__device__ float g_q[BS * H * E];
__device__ float g_km[BS * H * E];
__device__ float g_vm[BS * H * E];
__device__ float g_te[BS * 64];
__device__ float g_ta[BS * 64];
__device__ float g_S[RNN];
__device__ __align__(16) __nv_bfloat16 g_Abf[(size_t)BS * KTOT];
__device__ __align__(16) __nv_bfloat16 g_Wfbf[(size_t)RNN * KTOT];
__device__ __align__(16) __nv_bfloat16 g_Wvbf[2 * 64 * 64];
__device__ __align__(16) uint32_t g_WB[(size_t)2 * 192 * KF];

// ---------------- PTX helpers ----------------
__device__ __forceinline__ uint32_t smem_u32(const void* p) {
    uint32_t a;
    asm("{ .reg .u64 t; cvta.to.shared.u64 t, %1; cvt.u32.u64 %0, t; }" : "=r"(a) : "l"(p));
    return a;
}
__device__ __forceinline__ void cp16(uint32_t dst, const void* src) {
    asm volatile("cp.async.cg.shared.global [%0], [%1], 16;" :: "r"(dst), "l"(src) : "memory");
}
#define CP_COMMIT() asm volatile("cp.async.commit_group;" ::: "memory")
#define CP_WAIT(n)  asm volatile("cp.async.wait_group %0;" :: "n"(n) : "memory")

#define LDSM_X4(r0, r1, r2, r3, addr) \
    asm volatile("ldmatrix.sync.aligned.m8n8.x4.shared.b16 {%0,%1,%2,%3}, [%4];" \
                 : "=r"(r0), "=r"(r1), "=r"(r2), "=r"(r3) : "r"(addr))

#define MMA16816(d, a, b) \
    asm volatile("mma.sync.aligned.m16n8k16.row.col.f32.bf16.bf16.f32 " \
                 "{%0,%1,%2,%3}, {%4,%5,%6,%7}, {%8,%9}, {%0,%1,%2,%3};" \
                 : "+f"((d)[0]), "+f"((d)[1]), "+f"((d)[2]), "+f"((d)[3]) \
                 : "r"((a)[0]), "r"((a)[1]), "r"((a)[2]), "r"((a)[3]), \
                   "r"((b)[0]), "r"((b)[1]))

#define SWZ(x) ((x) ^ (((x) >> 3) & 0x70))

__device__ __forceinline__ uint32_t packbf2(float x, float y) {
    __nv_bfloat162 p = __floats2bfloat162_rn(x, y);
    return *(uint32_t*)&p;
}
__device__ __forceinline__ float dot4(float4 a, float4 b) {
    return a.x * b.x + a.y * b.y + a.z * b.z + a.w * b.w;
}

// =====================================================================
// K0: prep
// =====================================================================
__global__ __launch_bounds__(256) void k_prep(const float* __restrict__ Wf,
                                              const float* __restrict__ Wve,
                                              const float* __restrict__ Wva,
                                              const float* __restrict__ Wb1,
                                              const float* __restrict__ Wh1) {
    int r = blockIdx.x;
    int tid = threadIdx.x;
    if (r < 256) {
        __shared__ float row[8256];
        __shared__ float red[8];
        float s = 0.f;
        for (int i = tid; i < 8192; i += 256) {
            float v = Wf[(size_t)r * 8192 + i];
            row[i + (i >> 7)] = v;
            s += v;
        }
        #pragma unroll
        for (int o = 16; o; o >>= 1) s += __shfl_xor_sync(0xffffffffu, s, o);
        if ((tid & 31) == 0) red[tid >> 5] = s;
        __syncthreads();
        if (tid == 0) {
            float t = 0.f;
            #pragma unroll
            for (int j = 0; j < 8; j++) t += red[j];
            g_S[r] = t;
        }
        for (int i = tid; i < 8192; i += 256) {
            int na = i >> 6, e = i & 63;
            int src = e * 128 + na;
            g_Wfbf[(size_t)r * 8192 + i] = __float2bfloat16_rn(row[src + (src >> 7)]);
        }
    } else if (r == 256) {
        for (int i = tid; i < 8192; i += 256) {
            int sel = i >> 12, j = i & 4095;
            int e = j >> 6, hd = j & 63, h = hd >> 4, d = hd & 15;
            const float* W = sel ? Wva : Wve;
            g_Wvbf[i] = __float2bfloat16_rn(W[h * 1024 + e * 16 + d]);
        }
    } else {
        int n = r - 257;
        const float* W = (n < 64) ? (Wb1 + (size_t)n * IN) : (Wh1 + (size_t)(n - 64) * IN);
        uint32_t* d0 = g_WB + (size_t)n * KF;
        uint32_t* d1 = g_WB + (size_t)192 * KF + (size_t)n * KF;
        for (int k = tid; k < IN; k += 256) {
            float x = W[k];
            __nv_bfloat16 hi = __float2bfloat16_rn(x);
            __nv_bfloat16 lo = __float2bfloat16_rn(x - __bfloat162float(hi));
            __nv_bfloat162 p0; p0.x = hi; p0.y = hi;
            __nv_bfloat162 p1; p1.x = lo; p1.y = lo;
            d0[k] = *(uint32_t*)&p0;
            d1[k] = *(uint32_t*)&p1;
        }
    }
}

// =====================================================================
// K1: front GEMM (split-bf16 exact, obs converted in-register)
// =====================================================================
__global__ __launch_bounds__(256) void k_front_tc(const float* __restrict__ obs,
                                                  const float* __restrict__ bb1,
                                                  const float* __restrict__ bh1) {
    __shared__ __align__(128) char sm8[49152];
    const uint32_t sb = smem_u32(sm8);
    const int tid = threadIdx.x, lane = tid & 31, w = tid >> 5;
    const int bm = blockIdx.x * 64, bn = blockIdx.y * 64;
    const int wm = (w & 3) * 16, wn = (w >> 2) * 32;
    float d[4][4] = {};

    auto stageA = [&](int t, int buf) {
        #pragma unroll
        for (int i = 0; i < 2; i++) {
            int idx = tid + 256 * i;
            int row = idx >> 3, c16 = idx & 7;
            int k0 = t * 32 + c16 * 4;
            float4 v = make_float4(0.f, 0.f, 0.f, 0.f);
            if (k0 < IN) v = *(const float4*)(obs + (size_t)(bm + row) * IN + k0);
            uint32_t p[4];
            {
                float xs[4] = {v.x, v.y, v.z, v.w};
                #pragma unroll
                for (int j = 0; j < 4; j++) {
                    __nv_bfloat16 hi = __float2bfloat16_rn(xs[j]);
                    __nv_bfloat16 lo = __float2bfloat16_rn(xs[j] - __bfloat162float(hi));
                    __nv_bfloat162 pr; pr.x = hi; pr.y = lo;
                    p[j] = *(uint32_t*)&pr;
                }
            }
            *(uint4*)(sm8 + buf * 8192 + SWZ((uint32_t)(row * 128 + c16 * 16))) = *(uint4*)p;
        }
    };
    auto stageB = [&](int t, int buf) {
        #pragma unroll
        for (int i = 0; i < 2; i++) {
            int idx = tid + 256 * i;
            int row = idx >> 3, c16 = idx & 7;
            const uint32_t* s0 = g_WB + (size_t)(bn + row) * KF + t * 32 + c16 * 4;
            uint32_t off = SWZ((uint32_t)(row * 128 + c16 * 16));
            cp16(sb + 16384 + buf * 8192 + off, s0);
            cp16(sb + 32768 + buf * 8192 + off, s0 + (size_t)192 * KF);
        }
        CP_COMMIT();
    };

    stageA(0, 0);
    stageB(0, 0);
    for (int t = 0; t < 65; t++) {
        const int buf = t & 1;
        if (t < 64) {
            stageA(t + 1, buf ^ 1);
            stageB(t + 1, buf ^ 1);
            CP_WAIT(1);
        } else {
            CP_WAIT(0);
        }
        __syncthreads();
        const uint32_t ab = sb + buf * 8192;
        const uint32_t b0b = sb + 16384 + buf * 8192;
        const uint32_t b1b = sb + 32768 + buf * 8192;
        #pragma unroll
        for (int ks = 0; ks < 4; ks++) {
            uint32_t a[4];
            uint32_t byte = (uint32_t)((wm + (lane & 15)) * 128 + (lane >> 4) * 16 + ks * 32);
            LDSM_X4(a[0], a[1], a[2], a[3], ab + SWZ(byte));
            uint32_t b0[4][2], b1[4][2];
            #pragma unroll
            for (int nr = 0; nr < 2; nr++) {
                uint32_t by2 = (uint32_t)((wn + nr * 16 + (lane & 15)) * 128
                                          + (lane >> 4) * 16 + ks * 32);
                uint32_t r0, r1, r2, r3;
                LDSM_X4(r0, r1, r2, r3, b0b + SWZ(by2));
                b0[nr * 2][0] = r0; b0[nr * 2][1] = r2;
                b0[nr * 2 + 1][0] = r1; b0[nr * 2 + 1][1] = r3;
                LDSM_X4(r0, r1, r2, r3, b1b + SWZ(by2));
                b1[nr * 2][0] = r0; b1[nr * 2][1] = r2;
                b1[nr * 2 + 1][0] = r1; b1[nr * 2 + 1][1] = r3;
            }
            #pragma unroll
            for (int nt = 0; nt < 4; nt++) {
                MMA16816(d[nt], a, b0[nt]);
                MMA16816(d[nt], a, b1[nt]);
            }
        }
        __syncthreads();
    }

    #pragma unroll
    for (int half = 0; half < 2; half++) {
        int row = bm + wm + half * 8 + (lane >> 2);
        #pragma unroll
        for (int nt = 0; nt < 4; nt++) {
            int n = bn + wn + nt * 8 + (lane & 3) * 2;
            float bias0 = (n < 64) ? bb1[n] : bh1[n - 64];
            float bias1 = (n + 1 < 64) ? bb1[n + 1] : bh1[n + 1 - 64];
            float v0 = fmaxf(d[nt][half * 2 + 0] + bias0, 0.f);
            float v1 = fmaxf(d[nt][half * 2 + 1] + bias1, 0.f);
            *(float2*)&g_hid[row * 192 + n] = make_float2(v0, v1);
        }
    }
}

// =====================================================================
// K3: fused m-MLPs; mlp==0 also computes te/ta via mma
// =====================================================================
__global__ __launch_bounds__(256) void k_mlp(const float* __restrict__ obs,
                                             const float* __restrict__ Wq1, const float* __restrict__ bq1,
                                             const float* __restrict__ Wq2,
                                             const float* __restrict__ Wkm1, const float* __restrict__ bkm1,
                                             const float* __restrict__ Wkm2,
                                             const float* __restrict__ Wvm1, const float* __restrict__ bvm1,
                                             const float* __restrict__ Wvm2,
                                             const float* __restrict__ Wke,
                                             const float* __restrict__ Wka) {
    extern __shared__ __align__(128) char smp[];
    float* msm = (float*)smp;
    float* w1s = (float*)(smp + 12800);
    float* b1s = (float*)(smp + 25600);
    char* h1B = smp + 26112;
    char* w2B = smp + 58880;

    const int tid = threadIdx.x, lane = tid & 31;
    const int bm = blockIdx.x * 128;
    const int mlp = blockIdx.y >> 2, h = blockIdx.y & 3;
    const float* W1 = ((mlp == 0) ? Wq1 : (mlp == 1) ? Wkm1 : Wvm1) + h * HE * MF;
    const float* B1 = ((mlp == 0) ? bq1 : (mlp == 1) ? bkm1 : bvm1) + h * HE;
    const float* W2 = ((mlp == 0) ? Wq2 : (mlp == 1) ? Wkm2 : Wvm2) + h * E * HE;
    float* outp = (mlp == 0) ? g_q : (mlp == 1) ? g_km : g_vm;

    for (int i = tid; i < 128 * 24; i += 256) {
        int r = i / 24, f = i - r * 24;
        int col = (f < 4) ? f : (2032 + f);
        msm[r * 25 + f] = obs[(size_t)(bm + r) * IN + col];
    }
    for (int i = tid; i < 128 * 24; i += 256) {
        int g = i / 24, f = i - g * 24;
        w1s[g * 25 + f] = W1[g * 24 + f];
    }
    if (tid < 128) b1s[tid] = B1[tid];
    for (int i = tid; i < 1024; i += 256) {
        int e = i >> 4, g8 = (i & 15) * 8;
        int kk = g8 >> 6, wi = g8 & 63;
        const float* src = W2 + e * HE + g8;
        float4 v0 = *(const float4*)src;
        float4 v1 = *(const float4*)(src + 4);
        __nv_bfloat162 p[4];
        p[0] = __floats2bfloat162_rn(v0.x, v0.y);
        p[1] = __floats2bfloat162_rn(v0.z, v0.w);
        p[2] = __floats2bfloat162_rn(v1.x, v1.y);
        p[3] = __floats2bfloat162_rn(v1.z, v1.w);
        *(uint4*)(w2B + kk * 8192 + SWZ((uint32_t)(e * 128 + wi * 2))) = *(uint4*)p;
    }
    __syncthreads();

    {
        int r = tid & 127, chalf = tid >> 7;
        float mreg[24];
        #pragma unroll
        for (int f = 0; f < 24; f++) mreg[f] = msm[r * 25 + f];
        char* pan = h1B + chalf * 16384;
        #pragma unroll 4
        for (int c = 0; c < 64; c += 2) {
            int cc = chalf * 64 + c;
            float a0 = b1s[cc], a1 = b1s[cc + 1];
            const float* w0 = w1s + cc * 25;
            #pragma unroll
            for (int f = 0; f < 24; f++) {
                a0 += mreg[f] * w0[f];
                a1 += mreg[f] * w0[25 + f];
            }
            __nv_bfloat162 p = __floats2bfloat162_rn(fmaxf(a0, 0.f), fmaxf(a1, 0.f));
            *(__nv_bfloat162*)(pan + SWZ((uint32_t)(r * 128 + c * 2))) = p;
        }
    }
    __syncthreads();

    {
        int w = tid >> 5;
        int wm = (w & 1) * 64, wn = (w >> 1) * 16;
        uint32_t h1b = smem_u32(h1B);
        uint32_t w2b = smem_u32(w2B);
        float d[4][2][4] = {};
        #pragma unroll
        for (int kk = 0; kk < 2; kk++) {
            uint32_t ab = h1b + kk * 16384;
            uint32_t bb = w2b + kk * 8192;
            #pragma unroll
            for (int ks = 0; ks < 4; ks++) {
                uint32_t bfr[2][2];
                {
                    uint32_t by = (uint32_t)((wn + (lane & 15)) * 128 + (lane >> 4) * 16 + ks * 32);
                    uint32_t r0, r1, r2, r3;
                    LDSM_X4(r0, r1, r2, r3, bb + SWZ(by));
                    bfr[0][0] = r0; bfr[0][1] = r2;
                    bfr[1][0] = r1; bfr[1][1] = r3;
                }
                #pragma unroll
                for (int mt = 0; mt < 4; mt++) {
                    uint32_t a[4];
                    uint32_t by = (uint32_t)((wm + mt * 16 + (lane & 15)) * 128
                                             + (lane >> 4) * 16 + ks * 32);
                    LDSM_X4(a[0], a[1], a[2], a[3], ab + SWZ(by));
                    MMA16816(d[mt][0], a, bfr[0]);
                    MMA16816(d[mt][1], a, bfr[1]);
                }
            }
        }
        #pragma unroll
        for (int mt = 0; mt < 4; mt++)
            #pragma unroll
            for (int half = 0; half < 2; half++) {
                int row = bm + wm + mt * 16 + half * 8 + (lane >> 2);
                #pragma unroll
                for (int nt = 0; nt < 2; nt++) {
                    int e = wn + nt * 8 + (lane & 3) * 2;
                    *(float2*)&outp[(size_t)row * 256 + h * 64 + e] =
                        make_float2(d[mt][nt][half * 2], d[mt][nt][half * 2 + 1]);
                }
            }

        if (mlp == 0) {
            __syncthreads();
            char* qB = h1B;
            #pragma unroll
            for (int mt = 0; mt < 4; mt++)
                #pragma unroll
                for (int half = 0; half < 2; half++) {
                    int rl = wm + mt * 16 + half * 8 + (lane >> 2);
                    #pragma unroll
                    for (int nt = 0; nt < 2; nt++) {
                        int e = wn + nt * 8 + (lane & 3) * 2;
                        *(__nv_bfloat162*)(qB + SWZ((uint32_t)(rl * 128 + e * 2))) =
                            __floats2bfloat162_rn(d[mt][nt][half * 2], d[mt][nt][half * 2 + 1]);
                    }
                }
            for (int i = tid; i < 2048; i += 256) {
                int row = i >> 6, e = i & 63;
                int dd = row & 15;
                const float* Wk = (row < 16) ? Wke : Wka;
                *(__nv_bfloat16*)(w2B + SWZ((uint32_t)(row * 128 + e * 2))) =
                    __float2bfloat16_rn(Wk[h * 1024 + e * 16 + dd]);
            }
            __syncthreads();
            int wm2 = w * 16;
            uint32_t ab2 = smem_u32(qB);
            uint32_t bb3 = smem_u32(w2B);
            float dd[4][4] = {};
            #pragma unroll
            for (int ks = 0; ks < 4; ks++) {
                uint32_t a[4];
                uint32_t by = (uint32_t)((wm2 + (lane & 15)) * 128 + (lane >> 4) * 16 + ks * 32);
                LDSM_X4(a[0], a[1], a[2], a[3], ab2 + SWZ(by));
                uint32_t bfr[4][2];
                #pragma unroll
                for (int nr = 0; nr < 2; nr++) {
                    uint32_t by2 = (uint32_t)((nr * 16 + (lane & 15)) * 128
                                              + (lane >> 4) * 16 + ks * 32);
                    uint32_t r0, r1, r2, r3;
                    LDSM_X4(r0, r1, r2, r3, bb3 + SWZ(by2));
                    bfr[nr * 2][0] = r0; bfr[nr * 2][1] = r2;
                    bfr[nr * 2 + 1][0] = r1; bfr[nr * 2 + 1][1] = r3;
                }
                #pragma unroll
                for (int nt = 0; nt < 4; nt++) MMA16816(dd[nt], a, bfr[nt]);
            }
            #pragma unroll
            for (int half = 0; half < 2; half++) {
                int bglob = bm + wm2 + half * 8 + (lane >> 2);
                #pragma unroll
                for (int nt = 0; nt < 4; nt++) {
                    int n = nt * 8 + (lane & 3) * 2;
                    float v0 = dd[nt][half * 2] * 0.125f;
                    float v1 = dd[nt][half * 2 + 1] * 0.125f;
                    float* dst = (n < 16) ? (g_te + bglob * 64 + h * 16 + n)
                                          : (g_ta + bglob * 64 + h * 16 + (n - 16));
                    *(float2*)dst = make_float2(v0, v1);
                }
            }
        }
    }
}

// =====================================================================
// K4: attention, 2 batches per CTA; staged coalesced epilogue.
// =====================================================================
__global__ __launch_bounds__(256, 2) void k_attn(const float* __restrict__ obs,
                                                 const float* __restrict__ Wb2,
                                                 const float* __restrict__ bb2,
                                                 const float* __restrict__ Wh2,
                                                 const float* __restrict__ bh2) {
    __shared__ float ent2[2 * 2048];
    __shared__ float u2[2 * 512];
    __shared__ float vms2[2 * 256];
    __shared__ float tv2[2 * 128];
    __shared__ float whl2[2 * 8];
    __shared__ __align__(128) __nv_bfloat16 Wvs[128 * 64];

    const int tid = threadIdx.x;
    const int b0 = blockIdx.x * 2;
    const int lt = tid & 127, jb = tid >> 7;
    char* WvsB = (char*)Wvs;

    {
        const float4* src4 = (const float4*)(obs + (size_t)(b0 + jb) * IN + 4);
        float4* dst4 = (float4*)(ent2 + jb * 2048);
        #pragma unroll
        for (int i = lt; i < 508; i += 128) dst4[i] = src4[i];
        if (lt < 16) ent2[jb * 2048 + 2032 + lt] = 0.f;
    }
    {
        const uint4* wsrc = (const uint4*)g_Wvbf;
        #pragma unroll
        for (int i = tid; i < 1024; i += 256) {
            int row = i >> 3, c = i & 7;
            *(uint4*)(WvsB + SWZ((uint32_t)(row * 128 + c * 16))) = wsrc[i];
        }
    }
    vms2[jb * 256 + lt] = g_vm[(b0 + jb) * 256 + lt];
    vms2[jb * 256 + ((lt + 128) & 255)] = g_vm[(b0 + jb) * 256 + ((lt + 128) & 255)];

    {
        int b = b0 + jb;
        tv2[jb * 128 + lt] = ((lt < 64) ? g_te : g_ta)[b * 64 + (lt & 63)];
        int wl = lt >> 5, lane = lt & 31;
        float t = g_q[b * 256 + wl * 64 + lane]      * g_km[b * 256 + wl * 64 + lane]
                + g_q[b * 256 + wl * 64 + 32 + lane] * g_km[b * 256 + wl * 64 + 32 + lane];
        #pragma unroll
        for (int o = 16; o; o >>= 1) t += __shfl_xor_sync(0xffffffffu, t, o);
        if (lane == 0) whl2[jb * 8 + 4 + wl] = t * 0.125f;
        const float* hrow = g_hid + b * 192;
        float s = 0.f;
        #pragma unroll
        for (int j = lane; j < 128; j += 32) s += hrow[64 + j] * Wh2[wl * 128 + j];
        #pragma unroll
        for (int o = 16; o; o >>= 1) s += __shfl_xor_sync(0xffffffffu, s, o);
        if (lane == 0) whl2[jb * 8 + wl] = fabsf(s + bh2[wl]);
        if (wl == 0) {
            float bsum = hrow[lane] * Wb2[lane] + hrow[32 + lane] * Wb2[32 + lane];
            #pragma unroll
            for (int o = 16; o; o >>= 1) bsum += __shfl_xor_sync(0xffffffffu, bsum, o);
            if (lane == 0) g_bt[b] = bsum + bb2[0];
        }
    }
    __syncthreads();

    {
        const float* ent = ent2 + jb * 2048;
        const float* tv = tv2 + jb * 128;
        float* u = u2 + jb * 512;
        #pragma unroll
        for (int i = lt; i < 508; i += 128) {
            int h = i / 127, n = i - h * 127;
            const float4* tp = (const float4*)(tv + ((n < 64) ? 0 : 64) + h * 16);
            const float4* ep = (const float4*)(ent + n * 16);
            float s = dot4(ep[0], tp[0]) + dot4(ep[1], tp[1])
                    + dot4(ep[2], tp[2]) + dot4(ep[3], tp[3]);
            u[h * 128 + 1 + n] = s;
        }
        if (lt < 4) u[lt * 128] = whl2[jb * 8 + 4 + lt];
    }
    __syncthreads();

    {
        float* u = u2 + jb * 512;
        int h = lt >> 5, lane = lt & 31;
        float v0[4], m0 = -3.4e38f;
        #pragma unroll
        for (int j = 0; j < 4; j++) { v0[j] = u[h * 128 + lane + 32 * j]; m0 = fmaxf(m0, v0[j]); }
        #pragma unroll
        for (int o = 16; o; o >>= 1) m0 = fmaxf(m0, __shfl_xor_sync(0xffffffffu, m0, o));
        float ss = 0.f;
        #pragma unroll
        for (int j = 0; j < 4; j++) { v0[j] = expf(v0[j] - m0); ss += v0[j]; }
        #pragma unroll
        for (int o = 16; o; o >>= 1) ss += __shfl_xor_sync(0xffffffffu, ss, o);
        float sc = whl2[jb * 8 + h] / ss;
        #pragma unroll
        for (int j = 0; j < 4; j++) u[h * 128 + lane + 32 * j] = v0[j] * sc;
    }
    __syncthreads();

    // ---- tensor-core mix + staged coalesced epilogue
    {
        int w = tid >> 5, lane = tid & 31;
        int sel = w >> 2;
        int mbase = w * 16;
        int r = mbase + (lane >> 2);
        int c0 = (lane & 3) * 2;
        uint32_t wb = smem_u32(Wvs) + (uint32_t)sel * 8192u;

        float2 eA[2], eB[2], eC[2], eD[2];
        #pragma unroll
        for (int j = 0; j < 2; j++) {
            const float* ent = ent2 + j * 2048;
            eA[j] = *(float2*)&ent[r * 16 + c0];
            eB[j] = *(float2*)&ent[r * 16 + c0 + 8];
            eC[j] = *(float2*)&ent[(r + 8) * 16 + c0];
            eD[j] = *(float2*)&ent[(r + 8) * 16 + c0 + 8];
        }

        float d[2][8][4] = {};
        #pragma unroll
        for (int ks = 0; ks < 4; ks++) {
            uint32_t bfr[8][2];
            #pragma unroll
            for (int nr = 0; nr < 4; nr++) {
                uint32_t byte2 = (uint32_t)((nr * 16 + (lane & 15)) * 128 + (lane >> 4) * 16 + ks * 32);
                uint32_t r0, r1, r2, r3;
                LDSM_X4(r0, r1, r2, r3, wb + SWZ(byte2));
                bfr[nr * 2 + 0][0] = r0; bfr[nr * 2 + 0][1] = r2;
                bfr[nr * 2 + 1][0] = r1; bfr[nr * 2 + 1][1] = r3;
            }
            #pragma unroll
            for (int j = 0; j < 2; j++) {
                const float* u = u2 + j * 512;
                float ul = (r < 127)     ? u[ks * 128 + r + 1] : 0.f;
                float uh = (r + 8 < 127) ? u[ks * 128 + r + 9] : 0.f;
                uint32_t a[4];
                a[0] = packbf2(ul * eA[j].x, ul * eA[j].y);
                a[1] = packbf2(uh * eC[j].x, uh * eC[j].y);
                a[2] = packbf2(ul * eB[j].x, ul * eB[j].y);
                a[3] = packbf2(uh * eD[j].x, uh * eD[j].y);
                #pragma unroll
                for (int nt = 0; nt < 8; nt++) MMA16816(d[j][nt], a, bfr[nt]);
            }
        }

        // staged epilogue: reuse ent2 (16 KB) as SWZ bf16 tile [128 na][64 e]
        char* stg = (char*)ent2;
        #pragma unroll
        for (int j = 0; j < 2; j++) {
            __syncthreads();   // ent2 reads (e-frags) done / previous copy done
            if (tid < 64) {    // na = 0 row
                const float* u = u2 + j * 512;
                const float* vms = vms2 + j * 256;
                float s = 0.f;
                #pragma unroll
                for (int h = 0; h < 4; h++) s += u[h * 128] * vms[h * 64 + tid];
                *(__nv_bfloat16*)(stg + SWZ((uint32_t)(tid * 2))) = __float2bfloat16_rn(s);
            }
            #pragma unroll
            for (int half = 0; half < 2; half++) {
                int Arow = mbase + half * 8 + (lane >> 2);
                if (Arow < 127) {
                    int na = Arow + 1;
                    #pragma unroll
                    for (int nt = 0; nt < 8; nt++) {
                        int e = nt * 8 + (lane & 3) * 2;
                        *(uint32_t*)(stg + SWZ((uint32_t)(na * 128 + e * 2))) =
                            packbf2(d[j][nt][half * 2 + 0], d[j][nt][half * 2 + 1]);
                    }
                }
            }
            __syncthreads();
            uint4* dst = (uint4*)(g_Abf + (size_t)(b0 + j) * KTOT);
            #pragma unroll
            for (int i = tid; i < 1024; i += 256)
                dst[i] = *(uint4*)(stg + SWZ((uint32_t)(i * 16)));
        }
    }
}

// =====================================================================
// K5: bf16 mma GEMM, 3-stage cp.async pipeline:
//     out[4096,256] = Abf @ Wfbf^T + bt*S + bf
// =====================================================================
__global__ __launch_bounds__(256) void k_final_mma(const float* __restrict__ bfv,
                                                   float* __restrict__ out) {
    extern __shared__ __align__(128) char smf[];
    const uint32_t sb = smem_u32(smf);
    const int tid = threadIdx.x, lane = tid & 31, w = tid >> 5;
    const int bm = blockIdx.x * 64, bn = blockIdx.y * 128;
    const int wm = (w & 1) * 32, wn = (w >> 1) * 32;
    // A: 3 x 8 KB @ 0, B: 3 x 16 KB @ 24576

    float d[2][4][4] = {};

    auto loadChunk = [&](int t, int s) {
        const __nv_bfloat16* Asrc = g_Abf + (size_t)bm * KTOT + (size_t)t * 64;
        #pragma unroll
        for (int i = 0; i < 2; i++) {
            int idx = tid + 256 * i;
            int row = idx >> 3, c = idx & 7;
            cp16(sb + s * 8192 + SWZ((uint32_t)(row * 128 + c * 16)),
                 Asrc + (size_t)row * KTOT + c * 8);
        }
        const __nv_bfloat16* Bsrc = g_Wfbf + (size_t)bn * KTOT + (size_t)t * 64;
        #pragma unroll
        for (int i = 0; i < 4; i++) {
            int idx = tid + 256 * i;
            int row = idx >> 3, c = idx & 7;
            cp16(sb + 24576 + s * 16384 + SWZ((uint32_t)(row * 128 + c * 16)),
                 Bsrc + (size_t)row * KTOT + c * 8);
        }
        CP_COMMIT();
    };

    loadChunk(0, 0);
    loadChunk(1, 1);
    for (int t = 0; t < 128; t++) {
        const int s = t % 3;
        if (t + 2 < 128)      { loadChunk(t + 2, (t + 2) % 3); CP_WAIT(2); }
        else if (t + 1 < 128) { CP_WAIT(1); }
        else                  { CP_WAIT(0); }
        __syncthreads();

        const uint32_t abase = sb + s * 8192;
        const uint32_t bbase = sb + 24576 + s * 16384;
        #pragma unroll
        for (int ks = 0; ks < 4; ks++) {
            uint32_t a[2][4], b[4][2];
            #pragma unroll
            for (int mt = 0; mt < 2; mt++) {
                uint32_t byte = (uint32_t)((wm + mt * 16 + (lane & 15)) * 128
                                           + (lane >> 4) * 16 + ks * 32);
                LDSM_X4(a[mt][0], a[mt][1], a[mt][2], a[mt][3], abase + SWZ(byte));
            }
            #pragma unroll
            for (int nr = 0; nr < 2; nr++) {
                uint32_t byte = (uint32_t)((wn + nr * 16 + (lane & 15)) * 128
                                           + (lane >> 4) * 16 + ks * 32);
                uint32_t r0, r1, r2, r3;
                LDSM_X4(r0, r1, r2, r3, bbase + SWZ(byte));
                b[nr * 2 + 0][0] = r0; b[nr * 2 + 0][1] = r2;
                b[nr * 2 + 1][0] = r1; b[nr * 2 + 1][1] = r3;
            }
            #pragma unroll
            for (int mt = 0; mt < 2; mt++)
                #pragma unroll
                for (int nt = 0; nt < 4; nt++)
                    MMA16816(d[mt][nt], a[mt], b[nt]);
        }
        __syncthreads();
    }

    const int nbase = bn + wn + (lane & 3) * 2;
    #pragma unroll
    for (int mt = 0; mt < 2; mt++) {
        #pragma unroll
        for (int half = 0; half < 2; half++) {
            int row = bm + wm + mt * 16 + half * 8 + (lane >> 2);
            float btv = g_bt[row];
            #pragma unroll
            for (int nt = 0; nt < 4; nt++) {
                int col = nbase + nt * 8;
                float v0 = d[mt][nt][half * 2 + 0] + btv * g_S[col]     + bfv[col];
                float v1 = d[mt][nt][half * 2 + 1] + btv * g_S[col + 1] + bfv[col + 1];
                *(float2*)&out[(size_t)row * RNN + col] = make_float2(v0, v1);
            }
        }
    }
}

// =====================================================================
// launch
// =====================================================================
extern "C" void kernel_launch(void* const* d_in, const int* in_sizes, int n_in,
                              void* d_out, int out_size) {
    const float* obs  = (const float*)d_in[0];
    const float* Wq1  = (const float*)d_in[1];
    const float* bq1  = (const float*)d_in[2];
    const float* Wq2  = (const float*)d_in[3];
    const float* Wkm1 = (const float*)d_in[4];
    const float* bkm1 = (const float*)d_in[5];
    const float* Wkm2 = (const float*)d_in[6];
    const float* Wke  = (const float*)d_in[7];
    const float* Wka  = (const float*)d_in[8];
    const float* Wvm1 = (const float*)d_in[9];
    const float* bvm1 = (const float*)d_in[10];
    const float* Wvm2 = (const float*)d_in[11];
    const float* Wve  = (const float*)d_in[12];
    const float* Wva  = (const float*)d_in[13];
    const float* Wb1  = (const float*)d_in[14];
    const float* bb1  = (const float*)d_in[15];
    const float* Wb2  = (const float*)d_in[16];
    const float* bb2  = (const float*)d_in[17];
    const float* Wh1  = (const float*)d_in[18];
    const float* bh1  = (const float*)d_in[19];
    const float* Wh2  = (const float*)d_in[20];
    const float* bh2  = (const float*)d_in[21];
    const float* Wf   = (const float*)d_in[22];
    const float* bf   = (const float*)d_in[23];
    float* out = (float*)d_out;

    const int mlp_smem = 75264;
    const int final_smem = 24576 + 3 * 16384;   // 73728
    cudaFuncSetAttribute(k_mlp, cudaFuncAttributeMaxDynamicSharedMemorySize, mlp_smem);
    cudaFuncSetAttribute(k_final_mma, cudaFuncAttributeMaxDynamicSharedMemorySize, final_smem);

    k_prep<<<449, 256>>>(Wf, Wve, Wva, Wb1, Wh1);
    k_front_tc<<<dim3(64, 3), 256>>>(obs, bb1, bh1);
    k_mlp<<<dim3(32, 12), 256, mlp_smem>>>(obs, Wq1, bq1, Wq2, Wkm1, bkm1, Wkm2,
                                           Wvm1, bvm1, Wvm2, Wke, Wka);
    k_attn<<<2048, 256>>>(obs, Wb2, bb2, Wh2, bh2);
    k_final_mma<<<dim3(64, 2), 256, final_smem>>>(bf, out);
}

// round 12
// speedup vs baseline: 1.3009x; 1.1297x over previous
#include <cuda_runtime.h>
#include <cuda_bf16.h>
#include <cstdint>
#include <cstddef>

// ---------------- problem dims ----------------
#define BS 4096
#define IN 2056
#define MF 24
#define H 4
#define HE 128
#define E 64
#define NA 128
#define RNN 256
#define KTOT 8192
#define KF 2080

// ---------------- scratch ----------------
__device__ float g_hid[BS * 192];
__device__ float g_bt[BS];
__device__ float g_q[BS * H * E];
__device__ float g_km[BS * H * E];
__device__ float g_vm[BS * H * E];
__device__ float g_te[BS * 64];
__device__ float g_ta[BS * 64];
__device__ float g_S[RNN];
__device__ __align__(16) __nv_bfloat16 g_Abf[(size_t)BS * KTOT];
__device__ __align__(16) __nv_bfloat16 g_Wfbf[(size_t)RNN * KTOT];
__device__ __align__(16) __nv_bfloat16 g_Wvbf[2 * 64 * 64];
__device__ __align__(16) uint32_t g_WB[(size_t)2 * 192 * KF];

// ---------------- PTX helpers ----------------
__device__ __forceinline__ uint32_t smem_u32(const void* p) {
    uint32_t a;
    asm("{ .reg .u64 t; cvta.to.shared.u64 t, %1; cvt.u32.u64 %0, t; }" : "=r"(a) : "l"(p));
    return a;
}
__device__ __forceinline__ void cp16(uint32_t dst, const void* src) {
    asm volatile("cp.async.cg.shared.global [%0], [%1], 16;" :: "r"(dst), "l"(src) : "memory");
}
#define CP_COMMIT() asm volatile("cp.async.commit_group;" ::: "memory")
#define CP_WAIT(n)  asm volatile("cp.async.wait_group %0;" :: "n"(n) : "memory")

#define LDSM_X4(r0, r1, r2, r3, addr) \
    asm volatile("ldmatrix.sync.aligned.m8n8.x4.shared.b16 {%0,%1,%2,%3}, [%4];" \
                 : "=r"(r0), "=r"(r1), "=r"(r2), "=r"(r3) : "r"(addr))

#define MMA16816(d, a, b) \
    asm volatile("mma.sync.aligned.m16n8k16.row.col.f32.bf16.bf16.f32 " \
                 "{%0,%1,%2,%3}, {%4,%5,%6,%7}, {%8,%9}, {%0,%1,%2,%3};" \
                 : "+f"((d)[0]), "+f"((d)[1]), "+f"((d)[2]), "+f"((d)[3]) \
                 : "r"((a)[0]), "r"((a)[1]), "r"((a)[2]), "r"((a)[3]), \
                   "r"((b)[0]), "r"((b)[1]))

#define SWZ(x) ((x) ^ (((x) >> 3) & 0x70))

__device__ __forceinline__ uint32_t packbf2(float x, float y) {
    __nv_bfloat162 p = __floats2bfloat162_rn(x, y);
    return *(uint32_t*)&p;
}

// =====================================================================
// K0: merged prep + m-MLPs.
//   blocks 0..255   : Wf row -> permuted bf16 + S[r]
//   block 256       : flatten Wve/Wva
//   blocks 257..448 : front weights hi/lo
//   blocks 449..832 : m-MLP work (bm,mlp,h); mlp==0 also te/ta via mma
// =====================================================================
__global__ __launch_bounds__(256) void k_prep_mlp(
        const float* __restrict__ Wf,
        const float* __restrict__ Wve, const float* __restrict__ Wva,
        const float* __restrict__ Wb1, const float* __restrict__ Wh1,
        const float* __restrict__ obs,
        const float* __restrict__ Wq1, const float* __restrict__ bq1,
        const float* __restrict__ Wq2,
        const float* __restrict__ Wkm1, const float* __restrict__ bkm1,
        const float* __restrict__ Wkm2,
        const float* __restrict__ Wvm1, const float* __restrict__ bvm1,
        const float* __restrict__ Wvm2,
        const float* __restrict__ Wke, const float* __restrict__ Wka) {
    extern __shared__ __align__(128) char smp[];
    int r = blockIdx.x;
    int tid = threadIdx.x;
    if (r < 256) {
        float* row = (float*)smp;          // 8256 floats
        float* red = (float*)smp + 8256;   // 8
        float s = 0.f;
        for (int i = tid; i < 8192; i += 256) {
            float v = Wf[(size_t)r * 8192 + i];
            row[i + (i >> 7)] = v;
            s += v;
        }
        #pragma unroll
        for (int o = 16; o; o >>= 1) s += __shfl_xor_sync(0xffffffffu, s, o);
        if ((tid & 31) == 0) red[tid >> 5] = s;
        __syncthreads();
        if (tid == 0) {
            float t = 0.f;
            #pragma unroll
            for (int j = 0; j < 8; j++) t += red[j];
            g_S[r] = t;
        }
        for (int i = tid; i < 8192; i += 256) {
            int na = i >> 6, e = i & 63;
            int src = e * 128 + na;
            g_Wfbf[(size_t)r * 8192 + i] = __float2bfloat16_rn(row[src + (src >> 7)]);
        }
        return;
    }
    if (r == 256) {
        for (int i = tid; i < 8192; i += 256) {
            int sel = i >> 12, j = i & 4095;
            int e = j >> 6, hd = j & 63, h = hd >> 4, d = hd & 15;
            const float* W = sel ? Wva : Wve;
            g_Wvbf[i] = __float2bfloat16_rn(W[h * 1024 + e * 16 + d]);
        }
        return;
    }
    if (r < 449) {
        int n = r - 257;
        const float* W = (n < 64) ? (Wb1 + (size_t)n * IN) : (Wh1 + (size_t)(n - 64) * IN);
        uint32_t* d0 = g_WB + (size_t)n * KF;
        uint32_t* d1 = g_WB + (size_t)192 * KF + (size_t)n * KF;
        for (int k = tid; k < IN; k += 256) {
            float x = W[k];
            __nv_bfloat16 hi = __float2bfloat16_rn(x);
            __nv_bfloat16 lo = __float2bfloat16_rn(x - __bfloat162float(hi));
            __nv_bfloat162 p0; p0.x = hi; p0.y = hi;
            __nv_bfloat162 p1; p1.x = lo; p1.y = lo;
            d0[k] = *(uint32_t*)&p0;
            d1[k] = *(uint32_t*)&p1;
        }
        return;
    }
    // ---------------- m-MLP part ----------------
    {
        int idx = r - 449;                 // 0..383
        const int bm = (idx & 31) * 128;
        int yy = idx >> 5;                 // 0..11
        const int mlp = yy >> 2, h = yy & 3;
        const int lane = tid & 31;

        float* msm = (float*)smp;                    // 128*25
        float* w1s = (float*)(smp + 12800);
        float* b1s = (float*)(smp + 25600);
        char* h1B = smp + 26112;
        char* w2B = smp + 58880;

        const float* W1 = ((mlp == 0) ? Wq1 : (mlp == 1) ? Wkm1 : Wvm1) + h * HE * MF;
        const float* B1 = ((mlp == 0) ? bq1 : (mlp == 1) ? bkm1 : bvm1) + h * HE;
        const float* W2 = ((mlp == 0) ? Wq2 : (mlp == 1) ? Wkm2 : Wvm2) + h * E * HE;
        float* outp = (mlp == 0) ? g_q : (mlp == 1) ? g_km : g_vm;

        for (int i = tid; i < 128 * 24; i += 256) {
            int rr = i / 24, f = i - rr * 24;
            int col = (f < 4) ? f : (2032 + f);
            msm[rr * 25 + f] = obs[(size_t)(bm + rr) * IN + col];
        }
        for (int i = tid; i < 128 * 24; i += 256) {
            int g = i / 24, f = i - g * 24;
            w1s[g * 25 + f] = W1[g * 24 + f];
        }
        if (tid < 128) b1s[tid] = B1[tid];
        for (int i = tid; i < 1024; i += 256) {
            int e = i >> 4, g8 = (i & 15) * 8;
            int kk = g8 >> 6, wi = g8 & 63;
            const float* src = W2 + e * HE + g8;
            float4 v0 = *(const float4*)src;
            float4 v1 = *(const float4*)(src + 4);
            __nv_bfloat162 p[4];
            p[0] = __floats2bfloat162_rn(v0.x, v0.y);
            p[1] = __floats2bfloat162_rn(v0.z, v0.w);
            p[2] = __floats2bfloat162_rn(v1.x, v1.y);
            p[3] = __floats2bfloat162_rn(v1.z, v1.w);
            *(uint4*)(w2B + kk * 8192 + SWZ((uint32_t)(e * 128 + wi * 2))) = *(uint4*)p;
        }
        __syncthreads();

        {
            int rr = tid & 127, chalf = tid >> 7;
            float mreg[24];
            #pragma unroll
            for (int f = 0; f < 24; f++) mreg[f] = msm[rr * 25 + f];
            char* pan = h1B + chalf * 16384;
            #pragma unroll 4
            for (int c = 0; c < 64; c += 2) {
                int cc = chalf * 64 + c;
                float a0 = b1s[cc], a1 = b1s[cc + 1];
                const float* w0 = w1s + cc * 25;
                #pragma unroll
                for (int f = 0; f < 24; f++) {
                    a0 += mreg[f] * w0[f];
                    a1 += mreg[f] * w0[25 + f];
                }
                __nv_bfloat162 p = __floats2bfloat162_rn(fmaxf(a0, 0.f), fmaxf(a1, 0.f));
                *(__nv_bfloat162*)(pan + SWZ((uint32_t)(rr * 128 + c * 2))) = p;
            }
        }
        __syncthreads();

        {
            int w = tid >> 5;
            int wm = (w & 1) * 64, wn = (w >> 1) * 16;
            uint32_t h1b = smem_u32(h1B);
            uint32_t w2b = smem_u32(w2B);
            float d[4][2][4] = {};
            #pragma unroll
            for (int kk = 0; kk < 2; kk++) {
                uint32_t ab = h1b + kk * 16384;
                uint32_t bb = w2b + kk * 8192;
                #pragma unroll
                for (int ks = 0; ks < 4; ks++) {
                    uint32_t bfr[2][2];
                    {
                        uint32_t by = (uint32_t)((wn + (lane & 15)) * 128 + (lane >> 4) * 16 + ks * 32);
                        uint32_t r0, r1, r2, r3;
                        LDSM_X4(r0, r1, r2, r3, bb + SWZ(by));
                        bfr[0][0] = r0; bfr[0][1] = r2;
                        bfr[1][0] = r1; bfr[1][1] = r3;
                    }
                    #pragma unroll
                    for (int mt = 0; mt < 4; mt++) {
                        uint32_t a[4];
                        uint32_t by = (uint32_t)((wm + mt * 16 + (lane & 15)) * 128
                                                 + (lane >> 4) * 16 + ks * 32);
                        LDSM_X4(a[0], a[1], a[2], a[3], ab + SWZ(by));
                        MMA16816(d[mt][0], a, bfr[0]);
                        MMA16816(d[mt][1], a, bfr[1]);
                    }
                }
            }
            #pragma unroll
            for (int mt = 0; mt < 4; mt++)
                #pragma unroll
                for (int half = 0; half < 2; half++) {
                    int row = bm + wm + mt * 16 + half * 8 + (lane >> 2);
                    #pragma unroll
                    for (int nt = 0; nt < 2; nt++) {
                        int e = wn + nt * 8 + (lane & 3) * 2;
                        *(float2*)&outp[(size_t)row * 256 + h * 64 + e] =
                            make_float2(d[mt][nt][half * 2], d[mt][nt][half * 2 + 1]);
                    }
                }

            if (mlp == 0) {
                __syncthreads();
                char* qB = h1B;
                #pragma unroll
                for (int mt = 0; mt < 4; mt++)
                    #pragma unroll
                    for (int half = 0; half < 2; half++) {
                        int rl = wm + mt * 16 + half * 8 + (lane >> 2);
                        #pragma unroll
                        for (int nt = 0; nt < 2; nt++) {
                            int e = wn + nt * 8 + (lane & 3) * 2;
                            *(__nv_bfloat162*)(qB + SWZ((uint32_t)(rl * 128 + e * 2))) =
                                __floats2bfloat162_rn(d[mt][nt][half * 2], d[mt][nt][half * 2 + 1]);
                        }
                    }
                for (int i = tid; i < 2048; i += 256) {
                    int row = i >> 6, e = i & 63;
                    int dd = row & 15;
                    const float* Wk = (row < 16) ? Wke : Wka;
                    *(__nv_bfloat16*)(w2B + SWZ((uint32_t)(row * 128 + e * 2))) =
                        __float2bfloat16_rn(Wk[h * 1024 + e * 16 + dd]);
                }
                __syncthreads();
                int wm2 = w * 16;
                uint32_t ab2 = smem_u32(qB);
                uint32_t bb3 = smem_u32(w2B);
                float dd[4][4] = {};
                #pragma unroll
                for (int ks = 0; ks < 4; ks++) {
                    uint32_t a[4];
                    uint32_t by = (uint32_t)((wm2 + (lane & 15)) * 128 + (lane >> 4) * 16 + ks * 32);
                    LDSM_X4(a[0], a[1], a[2], a[3], ab2 + SWZ(by));
                    uint32_t bfr[4][2];
                    #pragma unroll
                    for (int nr = 0; nr < 2; nr++) {
                        uint32_t by2 = (uint32_t)((nr * 16 + (lane & 15)) * 128
                                                  + (lane >> 4) * 16 + ks * 32);
                        uint32_t r0, r1, r2, r3;
                        LDSM_X4(r0, r1, r2, r3, bb3 + SWZ(by2));
                        bfr[nr * 2][0] = r0; bfr[nr * 2][1] = r2;
                        bfr[nr * 2 + 1][0] = r1; bfr[nr * 2 + 1][1] = r3;
                    }
                    #pragma unroll
                    for (int nt = 0; nt < 4; nt++) MMA16816(dd[nt], a, bfr[nt]);
                }
                #pragma unroll
                for (int half = 0; half < 2; half++) {
                    int bglob = bm + wm2 + half * 8 + (lane >> 2);
                    #pragma unroll
                    for (int nt = 0; nt < 4; nt++) {
                        int n = nt * 8 + (lane & 3) * 2;
                        float v0 = dd[nt][half * 2] * 0.125f;
                        float v1 = dd[nt][half * 2 + 1] * 0.125f;
                        float* dst = (n < 16) ? (g_te + bglob * 64 + h * 16 + n)
                                              : (g_ta + bglob * 64 + h * 16 + (n - 16));
                        *(float2*)dst = make_float2(v0, v1);
                    }
                }
            }
        }
    }
}

// =====================================================================
// K1: front GEMM (split-bf16 exact), A-path software pipelined
// =====================================================================
__global__ __launch_bounds__(256) void k_front_tc(const float* __restrict__ obs,
                                                  const float* __restrict__ bb1,
                                                  const float* __restrict__ bh1) {
    __shared__ __align__(128) char sm8[49152];
    const uint32_t sb = smem_u32(sm8);
    const int tid = threadIdx.x, lane = tid & 31, w = tid >> 5;
    const int bm = blockIdx.x * 64, bn = blockIdx.y * 64;
    const int wm = (w & 3) * 16, wn = (w >> 2) * 32;
    float d[4][4] = {};

    const int arow0 = tid >> 3, ac16_0 = tid & 7;
    const int arow1 = (tid + 256) >> 3, ac16_1 = (tid + 256) & 7;
    float4 areg[2];

    auto ldA = [&](int t) {
        int k0 = t * 32 + ac16_0 * 4;
        areg[0] = (k0 < IN) ? *(const float4*)(obs + (size_t)(bm + arow0) * IN + k0)
                            : make_float4(0.f, 0.f, 0.f, 0.f);
        int k1 = t * 32 + ac16_1 * 4;
        areg[1] = (k1 < IN) ? *(const float4*)(obs + (size_t)(bm + arow1) * IN + k1)
                            : make_float4(0.f, 0.f, 0.f, 0.f);
    };
    auto stA = [&](int buf) {
        #pragma unroll
        for (int i = 0; i < 2; i++) {
            int row = i ? arow1 : arow0, c16 = i ? ac16_1 : ac16_0;
            float xs[4] = {areg[i].x, areg[i].y, areg[i].z, areg[i].w};
            uint32_t p[4];
            #pragma unroll
            for (int j = 0; j < 4; j++) {
                __nv_bfloat16 hi = __float2bfloat16_rn(xs[j]);
                __nv_bfloat16 lo = __float2bfloat16_rn(xs[j] - __bfloat162float(hi));
                __nv_bfloat162 pr; pr.x = hi; pr.y = lo;
                p[j] = *(uint32_t*)&pr;
            }
            *(uint4*)(sm8 + buf * 8192 + SWZ((uint32_t)(row * 128 + c16 * 16))) = *(uint4*)p;
        }
    };
    auto stageB = [&](int t, int buf) {
        #pragma unroll
        for (int i = 0; i < 2; i++) {
            int idx = tid + 256 * i;
            int row = idx >> 3, c16 = idx & 7;
            const uint32_t* s0 = g_WB + (size_t)(bn + row) * KF + t * 32 + c16 * 4;
            uint32_t off = SWZ((uint32_t)(row * 128 + c16 * 16));
            cp16(sb + 16384 + buf * 8192 + off, s0);
            cp16(sb + 32768 + buf * 8192 + off, s0 + (size_t)192 * KF);
        }
        CP_COMMIT();
    };

    ldA(0); stA(0);
    stageB(0, 0);
    ldA(1);
    for (int t = 0; t < 65; t++) {
        const int buf = t & 1;
        if (t < 64) {
            stA(buf ^ 1);          // stores chunk t+1 (areg)
            stageB(t + 1, buf ^ 1);
            CP_WAIT(1);
            if (t + 2 <= 64) ldA(t + 2);
        } else {
            CP_WAIT(0);
        }
        __syncthreads();
        const uint32_t ab = sb + buf * 8192;
        const uint32_t b0b = sb + 16384 + buf * 8192;
        const uint32_t b1b = sb + 32768 + buf * 8192;
        #pragma unroll
        for (int ks = 0; ks < 4; ks++) {
            uint32_t a[4];
            uint32_t byte = (uint32_t)((wm + (lane & 15)) * 128 + (lane >> 4) * 16 + ks * 32);
            LDSM_X4(a[0], a[1], a[2], a[3], ab + SWZ(byte));
            uint32_t b0[4][2], b1[4][2];
            #pragma unroll
            for (int nr = 0; nr < 2; nr++) {
                uint32_t by2 = (uint32_t)((wn + nr * 16 + (lane & 15)) * 128
                                          + (lane >> 4) * 16 + ks * 32);
                uint32_t r0, r1, r2, r3;
                LDSM_X4(r0, r1, r2, r3, b0b + SWZ(by2));
                b0[nr * 2][0] = r0; b0[nr * 2][1] = r2;
                b0[nr * 2 + 1][0] = r1; b0[nr * 2 + 1][1] = r3;
                LDSM_X4(r0, r1, r2, r3, b1b + SWZ(by2));
                b1[nr * 2][0] = r0; b1[nr * 2][1] = r2;
                b1[nr * 2 + 1][0] = r1; b1[nr * 2 + 1][1] = r3;
            }
            #pragma unroll
            for (int nt = 0; nt < 4; nt++) {
                MMA16816(d[nt], a, b0[nt]);
                MMA16816(d[nt], a, b1[nt]);
            }
        }
        __syncthreads();
    }

    #pragma unroll
    for (int half = 0; half < 2; half++) {
        int row = bm + wm + half * 8 + (lane >> 2);
        #pragma unroll
        for (int nt = 0; nt < 4; nt++) {
            int n = bn + wn + nt * 8 + (lane & 3) * 2;
            float bias0 = (n < 64) ? bb1[n] : bh1[n - 64];
            float bias1 = (n + 1 < 64) ? bb1[n + 1] : bh1[n + 1 - 64];
            float v0 = fmaxf(d[nt][half * 2 + 0] + bias0, 0.f);
            float v1 = fmaxf(d[nt][half * 2 + 1] + bias1, 0.f);
            *(float2*)&g_hid[row * 192 + n] = make_float2(v0, v1);
        }
    }
}

// =====================================================================
// K4: attention, 2 batches/CTA; logits via tensor core; staged epilogue
// =====================================================================
__global__ __launch_bounds__(256, 2) void k_attn(const float* __restrict__ obs,
                                                 const float* __restrict__ Wb2,
                                                 const float* __restrict__ bb2,
                                                 const float* __restrict__ Wh2,
                                                 const float* __restrict__ bh2) {
    __shared__ float ent2[2 * 2048];
    __shared__ float u2[2 * 512];
    __shared__ float vms2[2 * 256];
    __shared__ float tv2[2 * 128];
    __shared__ float whl2[2 * 8];
    __shared__ __align__(128) __nv_bfloat16 Wvs[128 * 64];

    const int tid = threadIdx.x;
    const int b0 = blockIdx.x * 2;
    const int lt = tid & 127, jb = tid >> 7;
    char* WvsB = (char*)Wvs;

    {
        const float4* src4 = (const float4*)(obs + (size_t)(b0 + jb) * IN + 4);
        float4* dst4 = (float4*)(ent2 + jb * 2048);
        #pragma unroll
        for (int i = lt; i < 508; i += 128) dst4[i] = src4[i];
        if (lt < 16) ent2[jb * 2048 + 2032 + lt] = 0.f;
    }
    {
        const uint4* wsrc = (const uint4*)g_Wvbf;
        #pragma unroll
        for (int i = tid; i < 1024; i += 256) {
            int row = i >> 3, c = i & 7;
            *(uint4*)(WvsB + SWZ((uint32_t)(row * 128 + c * 16))) = wsrc[i];
        }
    }
    vms2[jb * 256 + lt] = g_vm[(b0 + jb) * 256 + lt];
    vms2[jb * 256 + ((lt + 128) & 255)] = g_vm[(b0 + jb) * 256 + ((lt + 128) & 255)];

    {
        int b = b0 + jb;
        tv2[jb * 128 + lt] = ((lt < 64) ? g_te : g_ta)[b * 64 + (lt & 63)];
        int wl = lt >> 5, lane = lt & 31;
        float t = g_q[b * 256 + wl * 64 + lane]      * g_km[b * 256 + wl * 64 + lane]
                + g_q[b * 256 + wl * 64 + 32 + lane] * g_km[b * 256 + wl * 64 + 32 + lane];
        #pragma unroll
        for (int o = 16; o; o >>= 1) t += __shfl_xor_sync(0xffffffffu, t, o);
        if (lane == 0) whl2[jb * 8 + 4 + wl] = t * 0.125f;
        const float* hrow = g_hid + b * 192;
        float s = 0.f;
        #pragma unroll
        for (int j = lane; j < 128; j += 32) s += hrow[64 + j] * Wh2[wl * 128 + j];
        #pragma unroll
        for (int o = 16; o; o >>= 1) s += __shfl_xor_sync(0xffffffffu, s, o);
        if (lane == 0) whl2[jb * 8 + wl] = fabsf(s + bh2[wl]);
        if (wl == 0) {
            float bsum = hrow[lane] * Wb2[lane] + hrow[32 + lane] * Wb2[32 + lane];
            #pragma unroll
            for (int o = 16; o; o >>= 1) bsum += __shfl_xor_sync(0xffffffffu, bsum, o);
            if (lane == 0) g_bt[b] = bsum + bb2[0];
        }
    }
    __syncthreads();

    // ---- e-fragments (registers, reused by logits-mma AND mix-mma)
    const int w = tid >> 5, lane = tid & 31;
    const int sel = w >> 2;
    const int mbase = w * 16;
    const int r = mbase + (lane >> 2);
    const int c0 = (lane & 3) * 2;

    float2 eA[2], eB[2], eC[2], eD[2];
    #pragma unroll
    for (int j = 0; j < 2; j++) {
        const float* ent = ent2 + j * 2048;
        eA[j] = *(float2*)&ent[r * 16 + c0];
        eB[j] = *(float2*)&ent[r * 16 + c0 + 8];
        eC[j] = *(float2*)&ent[(r + 8) * 16 + c0];
        eD[j] = *(float2*)&ent[(r + 8) * 16 + c0 + 8];
    }

    // ---- logits via mma: logits[r][h] = sum_d ent[r][d] * tv[sel][h][d]
    {
        int hB = lane >> 2;                // B-frag column (head), valid < 4
        #pragma unroll
        for (int j = 0; j < 2; j++) {
            uint32_t a[4];
            a[0] = packbf2(eA[j].x, eA[j].y);
            a[1] = packbf2(eC[j].x, eC[j].y);
            a[2] = packbf2(eB[j].x, eB[j].y);
            a[3] = packbf2(eD[j].x, eD[j].y);
            uint32_t bfrag[2] = {0u, 0u};
            if (hB < 4) {
                const float* tvb = tv2 + j * 128 + sel * 64 + hB * 16;
                bfrag[0] = packbf2(tvb[c0], tvb[c0 + 1]);
                bfrag[1] = packbf2(tvb[c0 + 8], tvb[c0 + 9]);
            }
            float dl[4] = {0.f, 0.f, 0.f, 0.f};
            MMA16816(dl, a, bfrag);
            float* u = u2 + j * 512;
            if (c0 < 4) {
                if (r < 127) {
                    u[c0 * 128 + 1 + r] = dl[0];
                    u[(c0 + 1) * 128 + 1 + r] = dl[1];
                }
                if (r + 8 < 127) {
                    u[c0 * 128 + 9 + r] = dl[2];
                    u[(c0 + 1) * 128 + 9 + r] = dl[3];
                }
            }
        }
        if (lt < 4) u2[jb * 512 + lt * 128] = whl2[jb * 8 + 4 + lt];
    }
    __syncthreads();

    // ---- softmax in-place on u2
    {
        float* u = u2 + jb * 512;
        int h = lt >> 5, lane2 = lt & 31;
        float v0[4], m0 = -3.4e38f;
        #pragma unroll
        for (int j = 0; j < 4; j++) { v0[j] = u[h * 128 + lane2 + 32 * j]; m0 = fmaxf(m0, v0[j]); }
        #pragma unroll
        for (int o = 16; o; o >>= 1) m0 = fmaxf(m0, __shfl_xor_sync(0xffffffffu, m0, o));
        float ss = 0.f;
        #pragma unroll
        for (int j = 0; j < 4; j++) { v0[j] = expf(v0[j] - m0); ss += v0[j]; }
        #pragma unroll
        for (int o = 16; o; o >>= 1) ss += __shfl_xor_sync(0xffffffffu, ss, o);
        float sc = whl2[jb * 8 + h] / ss;
        #pragma unroll
        for (int j = 0; j < 4; j++) u[h * 128 + lane2 + 32 * j] = v0[j] * sc;
    }
    __syncthreads();

    // ---- tensor-core mix + staged coalesced epilogue
    {
        uint32_t wb = smem_u32(Wvs) + (uint32_t)sel * 8192u;

        float d[2][8][4] = {};
        #pragma unroll
        for (int ks = 0; ks < 4; ks++) {
            uint32_t bfr[8][2];
            #pragma unroll
            for (int nr = 0; nr < 4; nr++) {
                uint32_t byte2 = (uint32_t)((nr * 16 + (lane & 15)) * 128 + (lane >> 4) * 16 + ks * 32);
                uint32_t r0, r1, r2, r3;
                LDSM_X4(r0, r1, r2, r3, wb + SWZ(byte2));
                bfr[nr * 2 + 0][0] = r0; bfr[nr * 2 + 0][1] = r2;
                bfr[nr * 2 + 1][0] = r1; bfr[nr * 2 + 1][1] = r3;
            }
            #pragma unroll
            for (int j = 0; j < 2; j++) {
                const float* u = u2 + j * 512;
                float ul = (r < 127)     ? u[ks * 128 + r + 1] : 0.f;
                float uh = (r + 8 < 127) ? u[ks * 128 + r + 9] : 0.f;
                uint32_t a[4];
                a[0] = packbf2(ul * eA[j].x, ul * eA[j].y);
                a[1] = packbf2(uh * eC[j].x, uh * eC[j].y);
                a[2] = packbf2(ul * eB[j].x, ul * eB[j].y);
                a[3] = packbf2(uh * eD[j].x, uh * eD[j].y);
                #pragma unroll
                for (int nt = 0; nt < 8; nt++) MMA16816(d[j][nt], a, bfr[nt]);
            }
        }

        char* stg = (char*)ent2;
        #pragma unroll
        for (int j = 0; j < 2; j++) {
            __syncthreads();
            if (tid < 64) {
                const float* u = u2 + j * 512;
                const float* vms = vms2 + j * 256;
                float s = 0.f;
                #pragma unroll
                for (int h = 0; h < 4; h++) s += u[h * 128] * vms[h * 64 + tid];
                *(__nv_bfloat16*)(stg + SWZ((uint32_t)(tid * 2))) = __float2bfloat16_rn(s);
            }
            #pragma unroll
            for (int half = 0; half < 2; half++) {
                int Arow = mbase + half * 8 + (lane >> 2);
                if (Arow < 127) {
                    int na = Arow + 1;
                    #pragma unroll
                    for (int nt = 0; nt < 8; nt++) {
                        int e = nt * 8 + (lane & 3) * 2;
                        *(uint32_t*)(stg + SWZ((uint32_t)(na * 128 + e * 2))) =
                            packbf2(d[j][nt][half * 2 + 0], d[j][nt][half * 2 + 1]);
                    }
                }
            }
            __syncthreads();
            uint4* dst = (uint4*)(g_Abf + (size_t)(b0 + j) * KTOT);
            #pragma unroll
            for (int i = tid; i < 1024; i += 256)
                dst[i] = *(uint4*)(stg + SWZ((uint32_t)(i * 16)));
        }
    }
}

// =====================================================================
// K5: bf16 mma GEMM, 3-stage cp.async pipeline
// =====================================================================
__global__ __launch_bounds__(256) void k_final_mma(const float* __restrict__ bfv,
                                                   float* __restrict__ out) {
    extern __shared__ __align__(128) char smf[];
    const uint32_t sb = smem_u32(smf);
    const int tid = threadIdx.x, lane = tid & 31, w = tid >> 5;
    const int bm = blockIdx.x * 64, bn = blockIdx.y * 128;
    const int wm = (w & 1) * 32, wn = (w >> 1) * 32;

    float d[2][4][4] = {};

    auto loadChunk = [&](int t, int s) {
        const __nv_bfloat16* Asrc = g_Abf + (size_t)bm * KTOT + (size_t)t * 64;
        #pragma unroll
        for (int i = 0; i < 2; i++) {
            int idx = tid + 256 * i;
            int row = idx >> 3, c = idx & 7;
            cp16(sb + s * 8192 + SWZ((uint32_t)(row * 128 + c * 16)),
                 Asrc + (size_t)row * KTOT + c * 8);
        }
        const __nv_bfloat16* Bsrc = g_Wfbf + (size_t)bn * KTOT + (size_t)t * 64;
        #pragma unroll
        for (int i = 0; i < 4; i++) {
            int idx = tid + 256 * i;
            int row = idx >> 3, c = idx & 7;
            cp16(sb + 24576 + s * 16384 + SWZ((uint32_t)(row * 128 + c * 16)),
                 Bsrc + (size_t)row * KTOT + c * 8);
        }
        CP_COMMIT();
    };

    loadChunk(0, 0);
    loadChunk(1, 1);
    for (int t = 0; t < 128; t++) {
        const int s = t % 3;
        if (t + 2 < 128)      { loadChunk(t + 2, (t + 2) % 3); CP_WAIT(2); }
        else if (t + 1 < 128) { CP_WAIT(1); }
        else                  { CP_WAIT(0); }
        __syncthreads();

        const uint32_t abase = sb + s * 8192;
        const uint32_t bbase = sb + 24576 + s * 16384;
        #pragma unroll
        for (int ks = 0; ks < 4; ks++) {
            uint32_t a[2][4], b[4][2];
            #pragma unroll
            for (int mt = 0; mt < 2; mt++) {
                uint32_t byte = (uint32_t)((wm + mt * 16 + (lane & 15)) * 128
                                           + (lane >> 4) * 16 + ks * 32);
                LDSM_X4(a[mt][0], a[mt][1], a[mt][2], a[mt][3], abase + SWZ(byte));
            }
            #pragma unroll
            for (int nr = 0; nr < 2; nr++) {
                uint32_t byte = (uint32_t)((wn + nr * 16 + (lane & 15)) * 128
                                           + (lane >> 4) * 16 + ks * 32);
                uint32_t r0, r1, r2, r3;
                LDSM_X4(r0, r1, r2, r3, bbase + SWZ(byte));
                b[nr * 2 + 0][0] = r0; b[nr * 2 + 0][1] = r2;
                b[nr * 2 + 1][0] = r1; b[nr * 2 + 1][1] = r3;
            }
            #pragma unroll
            for (int mt = 0; mt < 2; mt++)
                #pragma unroll
                for (int nt = 0; nt < 4; nt++)
                    MMA16816(d[mt][nt], a[mt], b[nt]);
        }
        __syncthreads();
    }

    const int nbase = bn + wn + (lane & 3) * 2;
    #pragma unroll
    for (int mt = 0; mt < 2; mt++) {
        #pragma unroll
        for (int half = 0; half < 2; half++) {
            int row = bm + wm + mt * 16 + half * 8 + (lane >> 2);
            float btv = g_bt[row];
            #pragma unroll
            for (int nt = 0; nt < 4; nt++) {
                int col = nbase + nt * 8;
                float v0 = d[mt][nt][half * 2 + 0] + btv * g_S[col]     + bfv[col];
                float v1 = d[mt][nt][half * 2 + 1] + btv * g_S[col + 1] + bfv[col + 1];
                *(float2*)&out[(size_t)row * RNN + col] = make_float2(v0, v1);
            }
        }
    }
}

// =====================================================================
// launch
// =====================================================================
extern "C" void kernel_launch(void* const* d_in, const int* in_sizes, int n_in,
                              void* d_out, int out_size) {
    const float* obs  = (const float*)d_in[0];
    const float* Wq1  = (const float*)d_in[1];
    const float* bq1  = (const float*)d_in[2];
    const float* Wq2  = (const float*)d_in[3];
    const float* Wkm1 = (const float*)d_in[4];
    const float* bkm1 = (const float*)d_in[5];
    const float* Wkm2 = (const float*)d_in[6];
    const float* Wke  = (const float*)d_in[7];
    const float* Wka  = (const float*)d_in[8];
    const float* Wvm1 = (const float*)d_in[9];
    const float* bvm1 = (const float*)d_in[10];
    const float* Wvm2 = (const float*)d_in[11];
    const float* Wve  = (const float*)d_in[12];
    const float* Wva  = (const float*)d_in[13];
    const float* Wb1  = (const float*)d_in[14];
    const float* bb1  = (const float*)d_in[15];
    const float* Wb2  = (const float*)d_in[16];
    const float* bb2  = (const float*)d_in[17];
    const float* Wh1  = (const float*)d_in[18];
    const float* bh1  = (const float*)d_in[19];
    const float* Wh2  = (const float*)d_in[20];
    const float* bh2  = (const float*)d_in[21];
    const float* Wf   = (const float*)d_in[22];
    const float* bf   = (const float*)d_in[23];
    float* out = (float*)d_out;

    const int pm_smem = 75264;
    const int final_smem = 24576 + 3 * 16384;
    cudaFuncSetAttribute(k_prep_mlp, cudaFuncAttributeMaxDynamicSharedMemorySize, pm_smem);
    cudaFuncSetAttribute(k_final_mma, cudaFuncAttributeMaxDynamicSharedMemorySize, final_smem);

    k_prep_mlp<<<833, 256, pm_smem>>>(Wf, Wve, Wva, Wb1, Wh1, obs,
                                      Wq1, bq1, Wq2, Wkm1, bkm1, Wkm2,
                                      Wvm1, bvm1, Wvm2, Wke, Wka);
    k_front_tc<<<dim3(64, 3), 256>>>(obs, bb1, bh1);
    k_attn<<<2048, 256>>>(obs, Wb2, bb2, Wh2, bh2);
    k_final_mma<<<dim3(64, 2), 256, final_smem>>>(bf, out);
}

// round 13
// speedup vs baseline: 1.3288x; 1.0215x over previous
#include <cuda_runtime.h>
#include <cuda_bf16.h>
#include <cstdint>
#include <cstddef>

// ---------------- problem dims ----------------
#define BS 4096
#define IN 2056
#define MF 24
#define H 4
#define HE 128
#define E 64
#define NA 128
#define RNN 256
#define KTOT 8192
#define KF 2080

// ---------------- scratch ----------------
__device__ float g_hid[BS * 192];
__device__ float g_bt[BS];
__device__ float g_q[BS * H * E];
__device__ float g_km[BS * H * E];
__device__ float g_vm[BS * H * E];
__device__ float g_te[BS * 64];
__device__ float g_ta[BS * 64];
__device__ float g_S[RNN];
__device__ float g_part0[(size_t)BS * RNN];
__device__ float g_part1[(size_t)BS * RNN];
__device__ __align__(16) __nv_bfloat16 g_Abf[(size_t)BS * KTOT];
__device__ __align__(16) __nv_bfloat16 g_Wfbf[(size_t)RNN * KTOT];
__device__ __align__(16) __nv_bfloat16 g_Wvbf[2 * 64 * 64];
__device__ __align__(16) uint32_t g_WB[(size_t)2 * 192 * KF];

// ---------------- PTX helpers ----------------
__device__ __forceinline__ uint32_t smem_u32(const void* p) {
    uint32_t a;
    asm("{ .reg .u64 t; cvta.to.shared.u64 t, %1; cvt.u32.u64 %0, t; }" : "=r"(a) : "l"(p));
    return a;
}
__device__ __forceinline__ void cp16(uint32_t dst, const void* src) {
    asm volatile("cp.async.cg.shared.global [%0], [%1], 16;" :: "r"(dst), "l"(src) : "memory");
}
#define CP_COMMIT() asm volatile("cp.async.commit_group;" ::: "memory")
#define CP_WAIT(n)  asm volatile("cp.async.wait_group %0;" :: "n"(n) : "memory")

#define LDSM_X4(r0, r1, r2, r3, addr) \
    asm volatile("ldmatrix.sync.aligned.m8n8.x4.shared.b16 {%0,%1,%2,%3}, [%4];" \
                 : "=r"(r0), "=r"(r1), "=r"(r2), "=r"(r3) : "r"(addr))

#define MMA16816(d, a, b) \
    asm volatile("mma.sync.aligned.m16n8k16.row.col.f32.bf16.bf16.f32 " \
                 "{%0,%1,%2,%3}, {%4,%5,%6,%7}, {%8,%9}, {%0,%1,%2,%3};" \
                 : "+f"((d)[0]), "+f"((d)[1]), "+f"((d)[2]), "+f"((d)[3]) \
                 : "r"((a)[0]), "r"((a)[1]), "r"((a)[2]), "r"((a)[3]), \
                   "r"((b)[0]), "r"((b)[1]))

#define SWZ(x) ((x) ^ (((x) >> 3) & 0x70))

__device__ __forceinline__ uint32_t packbf2(float x, float y) {
    __nv_bfloat162 p = __floats2bfloat162_rn(x, y);
    return *(uint32_t*)&p;
}

// =====================================================================
// K0: merged prep + m-MLPs.
// =====================================================================
__global__ __launch_bounds__(256) void k_prep_mlp(
        const float* __restrict__ Wf,
        const float* __restrict__ Wve, const float* __restrict__ Wva,
        const float* __restrict__ Wb1, const float* __restrict__ Wh1,
        const float* __restrict__ obs,
        const float* __restrict__ Wq1, const float* __restrict__ bq1,
        const float* __restrict__ Wq2,
        const float* __restrict__ Wkm1, const float* __restrict__ bkm1,
        const float* __restrict__ Wkm2,
        const float* __restrict__ Wvm1, const float* __restrict__ bvm1,
        const float* __restrict__ Wvm2,
        const float* __restrict__ Wke, const float* __restrict__ Wka) {
    extern __shared__ __align__(128) char smp[];
    int r = blockIdx.x;
    int tid = threadIdx.x;
    if (r < 256) {
        float* row = (float*)smp;
        float* red = (float*)smp + 8256;
        float s = 0.f;
        for (int i = tid; i < 8192; i += 256) {
            float v = Wf[(size_t)r * 8192 + i];
            row[i + (i >> 7)] = v;
            s += v;
        }
        #pragma unroll
        for (int o = 16; o; o >>= 1) s += __shfl_xor_sync(0xffffffffu, s, o);
        if ((tid & 31) == 0) red[tid >> 5] = s;
        __syncthreads();
        if (tid == 0) {
            float t = 0.f;
            #pragma unroll
            for (int j = 0; j < 8; j++) t += red[j];
            g_S[r] = t;
        }
        for (int i = tid; i < 8192; i += 256) {
            int na = i >> 6, e = i & 63;
            int src = e * 128 + na;
            g_Wfbf[(size_t)r * 8192 + i] = __float2bfloat16_rn(row[src + (src >> 7)]);
        }
        return;
    }
    if (r == 256) {
        for (int i = tid; i < 8192; i += 256) {
            int sel = i >> 12, j = i & 4095;
            int e = j >> 6, hd = j & 63, h = hd >> 4, d = hd & 15;
            const float* W = sel ? Wva : Wve;
            g_Wvbf[i] = __float2bfloat16_rn(W[h * 1024 + e * 16 + d]);
        }
        return;
    }
    if (r < 449) {
        int n = r - 257;
        const float* W = (n < 64) ? (Wb1 + (size_t)n * IN) : (Wh1 + (size_t)(n - 64) * IN);
        uint32_t* d0 = g_WB + (size_t)n * KF;
        uint32_t* d1 = g_WB + (size_t)192 * KF + (size_t)n * KF;
        for (int k = tid; k < IN; k += 256) {
            float x = W[k];
            __nv_bfloat16 hi = __float2bfloat16_rn(x);
            __nv_bfloat16 lo = __float2bfloat16_rn(x - __bfloat162float(hi));
            __nv_bfloat162 p0; p0.x = hi; p0.y = hi;
            __nv_bfloat162 p1; p1.x = lo; p1.y = lo;
            d0[k] = *(uint32_t*)&p0;
            d1[k] = *(uint32_t*)&p1;
        }
        return;
    }
    // ---------------- m-MLP part ----------------
    {
        int idx = r - 449;
        const int bm = (idx & 31) * 128;
        int yy = idx >> 5;
        const int mlp = yy >> 2, h = yy & 3;
        const int lane = tid & 31;

        float* msm = (float*)smp;
        float* w1s = (float*)(smp + 12800);
        float* b1s = (float*)(smp + 25600);
        char* h1B = smp + 26112;
        char* w2B = smp + 58880;

        const float* W1 = ((mlp == 0) ? Wq1 : (mlp == 1) ? Wkm1 : Wvm1) + h * HE * MF;
        const float* B1 = ((mlp == 0) ? bq1 : (mlp == 1) ? bkm1 : bvm1) + h * HE;
        const float* W2 = ((mlp == 0) ? Wq2 : (mlp == 1) ? Wkm2 : Wvm2) + h * E * HE;
        float* outp = (mlp == 0) ? g_q : (mlp == 1) ? g_km : g_vm;

        for (int i = tid; i < 128 * 24; i += 256) {
            int rr = i / 24, f = i - rr * 24;
            int col = (f < 4) ? f : (2032 + f);
            msm[rr * 25 + f] = obs[(size_t)(bm + rr) * IN + col];
        }
        for (int i = tid; i < 128 * 24; i += 256) {
            int g = i / 24, f = i - g * 24;
            w1s[g * 25 + f] = W1[g * 24 + f];
        }
        if (tid < 128) b1s[tid] = B1[tid];
        for (int i = tid; i < 1024; i += 256) {
            int e = i >> 4, g8 = (i & 15) * 8;
            int kk = g8 >> 6, wi = g8 & 63;
            const float* src = W2 + e * HE + g8;
            float4 v0 = *(const float4*)src;
            float4 v1 = *(const float4*)(src + 4);
            __nv_bfloat162 p[4];
            p[0] = __floats2bfloat162_rn(v0.x, v0.y);
            p[1] = __floats2bfloat162_rn(v0.z, v0.w);
            p[2] = __floats2bfloat162_rn(v1.x, v1.y);
            p[3] = __floats2bfloat162_rn(v1.z, v1.w);
            *(uint4*)(w2B + kk * 8192 + SWZ((uint32_t)(e * 128 + wi * 2))) = *(uint4*)p;
        }
        __syncthreads();

        {
            int rr = tid & 127, chalf = tid >> 7;
            float mreg[24];
            #pragma unroll
            for (int f = 0; f < 24; f++) mreg[f] = msm[rr * 25 + f];
            char* pan = h1B + chalf * 16384;
            #pragma unroll 4
            for (int c = 0; c < 64; c += 2) {
                int cc = chalf * 64 + c;
                float a0 = b1s[cc], a1 = b1s[cc + 1];
                const float* w0 = w1s + cc * 25;
                #pragma unroll
                for (int f = 0; f < 24; f++) {
                    a0 += mreg[f] * w0[f];
                    a1 += mreg[f] * w0[25 + f];
                }
                __nv_bfloat162 p = __floats2bfloat162_rn(fmaxf(a0, 0.f), fmaxf(a1, 0.f));
                *(__nv_bfloat162*)(pan + SWZ((uint32_t)(rr * 128 + c * 2))) = p;
            }
        }
        __syncthreads();

        {
            int w = tid >> 5;
            int wm = (w & 1) * 64, wn = (w >> 1) * 16;
            uint32_t h1b = smem_u32(h1B);
            uint32_t w2b = smem_u32(w2B);
            float d[4][2][4] = {};
            #pragma unroll
            for (int kk = 0; kk < 2; kk++) {
                uint32_t ab = h1b + kk * 16384;
                uint32_t bb = w2b + kk * 8192;
                #pragma unroll
                for (int ks = 0; ks < 4; ks++) {
                    uint32_t bfr[2][2];
                    {
                        uint32_t by = (uint32_t)((wn + (lane & 15)) * 128 + (lane >> 4) * 16 + ks * 32);
                        uint32_t r0, r1, r2, r3;
                        LDSM_X4(r0, r1, r2, r3, bb + SWZ(by));
                        bfr[0][0] = r0; bfr[0][1] = r2;
                        bfr[1][0] = r1; bfr[1][1] = r3;
                    }
                    #pragma unroll
                    for (int mt = 0; mt < 4; mt++) {
                        uint32_t a[4];
                        uint32_t by = (uint32_t)((wm + mt * 16 + (lane & 15)) * 128
                                                 + (lane >> 4) * 16 + ks * 32);
                        LDSM_X4(a[0], a[1], a[2], a[3], ab + SWZ(by));
                        MMA16816(d[mt][0], a, bfr[0]);
                        MMA16816(d[mt][1], a, bfr[1]);
                    }
                }
            }
            #pragma unroll
            for (int mt = 0; mt < 4; mt++)
                #pragma unroll
                for (int half = 0; half < 2; half++) {
                    int row = bm + wm + mt * 16 + half * 8 + (lane >> 2);
                    #pragma unroll
                    for (int nt = 0; nt < 2; nt++) {
                        int e = wn + nt * 8 + (lane & 3) * 2;
                        *(float2*)&outp[(size_t)row * 256 + h * 64 + e] =
                            make_float2(d[mt][nt][half * 2], d[mt][nt][half * 2 + 1]);
                    }
                }

            if (mlp == 0) {
                __syncthreads();
                char* qB = h1B;
                #pragma unroll
                for (int mt = 0; mt < 4; mt++)
                    #pragma unroll
                    for (int half = 0; half < 2; half++) {
                        int rl = wm + mt * 16 + half * 8 + (lane >> 2);
                        #pragma unroll
                        for (int nt = 0; nt < 2; nt++) {
                            int e = wn + nt * 8 + (lane & 3) * 2;
                            *(__nv_bfloat162*)(qB + SWZ((uint32_t)(rl * 128 + e * 2))) =
                                __floats2bfloat162_rn(d[mt][nt][half * 2], d[mt][nt][half * 2 + 1]);
                        }
                    }
                for (int i = tid; i < 2048; i += 256) {
                    int row = i >> 6, e = i & 63;
                    int dd = row & 15;
                    const float* Wk = (row < 16) ? Wke : Wka;
                    *(__nv_bfloat16*)(w2B + SWZ((uint32_t)(row * 128 + e * 2))) =
                        __float2bfloat16_rn(Wk[h * 1024 + e * 16 + dd]);
                }
                __syncthreads();
                int wm2 = w * 16;
                uint32_t ab2 = smem_u32(qB);
                uint32_t bb3 = smem_u32(w2B);
                float dd[4][4] = {};
                #pragma unroll
                for (int ks = 0; ks < 4; ks++) {
                    uint32_t a[4];
                    uint32_t by = (uint32_t)((wm2 + (lane & 15)) * 128 + (lane >> 4) * 16 + ks * 32);
                    LDSM_X4(a[0], a[1], a[2], a[3], ab2 + SWZ(by));
                    uint32_t bfr[4][2];
                    #pragma unroll
                    for (int nr = 0; nr < 2; nr++) {
                        uint32_t by2 = (uint32_t)((nr * 16 + (lane & 15)) * 128
                                                  + (lane >> 4) * 16 + ks * 32);
                        uint32_t r0, r1, r2, r3;
                        LDSM_X4(r0, r1, r2, r3, bb3 + SWZ(by2));
                        bfr[nr * 2][0] = r0; bfr[nr * 2][1] = r2;
                        bfr[nr * 2 + 1][0] = r1; bfr[nr * 2 + 1][1] = r3;
                    }
                    #pragma unroll
                    for (int nt = 0; nt < 4; nt++) MMA16816(dd[nt], a, bfr[nt]);
                }
                #pragma unroll
                for (int half = 0; half < 2; half++) {
                    int bglob = bm + wm2 + half * 8 + (lane >> 2);
                    #pragma unroll
                    for (int nt = 0; nt < 4; nt++) {
                        int n = nt * 8 + (lane & 3) * 2;
                        float v0 = dd[nt][half * 2] * 0.125f;
                        float v1 = dd[nt][half * 2 + 1] * 0.125f;
                        float* dst = (n < 16) ? (g_te + bglob * 64 + h * 16 + n)
                                              : (g_ta + bglob * 64 + h * 16 + (n - 16));
                        *(float2*)dst = make_float2(v0, v1);
                    }
                }
            }
        }
    }
}

// =====================================================================
// K1: front GEMM (split-bf16 exact), A-path software pipelined
// =====================================================================
__global__ __launch_bounds__(256) void k_front_tc(const float* __restrict__ obs,
                                                  const float* __restrict__ bb1,
                                                  const float* __restrict__ bh1) {
    __shared__ __align__(128) char sm8[49152];
    const uint32_t sb = smem_u32(sm8);
    const int tid = threadIdx.x, lane = tid & 31, w = tid >> 5;
    const int bm = blockIdx.x * 64, bn = blockIdx.y * 64;
    const int wm = (w & 3) * 16, wn = (w >> 2) * 32;
    float d[4][4] = {};

    const int arow0 = tid >> 3, ac16_0 = tid & 7;
    const int arow1 = (tid + 256) >> 3, ac16_1 = (tid + 256) & 7;
    float4 areg[2];

    auto ldA = [&](int t) {
        int k0 = t * 32 + ac16_0 * 4;
        areg[0] = (k0 < IN) ? *(const float4*)(obs + (size_t)(bm + arow0) * IN + k0)
                            : make_float4(0.f, 0.f, 0.f, 0.f);
        int k1 = t * 32 + ac16_1 * 4;
        areg[1] = (k1 < IN) ? *(const float4*)(obs + (size_t)(bm + arow1) * IN + k1)
                            : make_float4(0.f, 0.f, 0.f, 0.f);
    };
    auto stA = [&](int buf) {
        #pragma unroll
        for (int i = 0; i < 2; i++) {
            int row = i ? arow1 : arow0, c16 = i ? ac16_1 : ac16_0;
            float xs[4] = {areg[i].x, areg[i].y, areg[i].z, areg[i].w};
            uint32_t p[4];
            #pragma unroll
            for (int j = 0; j < 4; j++) {
                __nv_bfloat16 hi = __float2bfloat16_rn(xs[j]);
                __nv_bfloat16 lo = __float2bfloat16_rn(xs[j] - __bfloat162float(hi));
                __nv_bfloat162 pr; pr.x = hi; pr.y = lo;
                p[j] = *(uint32_t*)&pr;
            }
            *(uint4*)(sm8 + buf * 8192 + SWZ((uint32_t)(row * 128 + c16 * 16))) = *(uint4*)p;
        }
    };
    auto stageB = [&](int t, int buf) {
        #pragma unroll
        for (int i = 0; i < 2; i++) {
            int idx = tid + 256 * i;
            int row = idx >> 3, c16 = idx & 7;
            const uint32_t* s0 = g_WB + (size_t)(bn + row) * KF + t * 32 + c16 * 4;
            uint32_t off = SWZ((uint32_t)(row * 128 + c16 * 16));
            cp16(sb + 16384 + buf * 8192 + off, s0);
            cp16(sb + 32768 + buf * 8192 + off, s0 + (size_t)192 * KF);
        }
        CP_COMMIT();
    };

    ldA(0); stA(0);
    stageB(0, 0);
    ldA(1);
    for (int t = 0; t < 65; t++) {
        const int buf = t & 1;
        if (t < 64) {
            stA(buf ^ 1);
            stageB(t + 1, buf ^ 1);
            CP_WAIT(1);
            if (t + 2 <= 64) ldA(t + 2);
        } else {
            CP_WAIT(0);
        }
        __syncthreads();
        const uint32_t ab = sb + buf * 8192;
        const uint32_t b0b = sb + 16384 + buf * 8192;
        const uint32_t b1b = sb + 32768 + buf * 8192;
        #pragma unroll
        for (int ks = 0; ks < 4; ks++) {
            uint32_t a[4];
            uint32_t byte = (uint32_t)((wm + (lane & 15)) * 128 + (lane >> 4) * 16 + ks * 32);
            LDSM_X4(a[0], a[1], a[2], a[3], ab + SWZ(byte));
            uint32_t b0[4][2], b1[4][2];
            #pragma unroll
            for (int nr = 0; nr < 2; nr++) {
                uint32_t by2 = (uint32_t)((wn + nr * 16 + (lane & 15)) * 128
                                          + (lane >> 4) * 16 + ks * 32);
                uint32_t r0, r1, r2, r3;
                LDSM_X4(r0, r1, r2, r3, b0b + SWZ(by2));
                b0[nr * 2][0] = r0; b0[nr * 2][1] = r2;
                b0[nr * 2 + 1][0] = r1; b0[nr * 2 + 1][1] = r3;
                LDSM_X4(r0, r1, r2, r3, b1b + SWZ(by2));
                b1[nr * 2][0] = r0; b1[nr * 2][1] = r2;
                b1[nr * 2 + 1][0] = r1; b1[nr * 2 + 1][1] = r3;
            }
            #pragma unroll
            for (int nt = 0; nt < 4; nt++) {
                MMA16816(d[nt], a, b0[nt]);
                MMA16816(d[nt], a, b1[nt]);
            }
        }
        __syncthreads();
    }

    #pragma unroll
    for (int half = 0; half < 2; half++) {
        int row = bm + wm + half * 8 + (lane >> 2);
        #pragma unroll
        for (int nt = 0; nt < 4; nt++) {
            int n = bn + wn + nt * 8 + (lane & 3) * 2;
            float bias0 = (n < 64) ? bb1[n] : bh1[n - 64];
            float bias1 = (n + 1 < 64) ? bb1[n + 1] : bh1[n + 1 - 64];
            float v0 = fmaxf(d[nt][half * 2 + 0] + bias0, 0.f);
            float v1 = fmaxf(d[nt][half * 2 + 1] + bias1, 0.f);
            *(float2*)&g_hid[row * 192 + n] = make_float2(v0, v1);
        }
    }
}

// =====================================================================
// K4: attention, 2 batches/CTA; logits via tensor core; staged epilogue
// =====================================================================
__global__ __launch_bounds__(256, 2) void k_attn(const float* __restrict__ obs,
                                                 const float* __restrict__ Wb2,
                                                 const float* __restrict__ bb2,
                                                 const float* __restrict__ Wh2,
                                                 const float* __restrict__ bh2) {
    __shared__ float ent2[2 * 2048];
    __shared__ float u2[2 * 512];
    __shared__ float vms2[2 * 256];
    __shared__ float tv2[2 * 128];
    __shared__ float whl2[2 * 8];
    __shared__ __align__(128) __nv_bfloat16 Wvs[128 * 64];

    const int tid = threadIdx.x;
    const int b0 = blockIdx.x * 2;
    const int lt = tid & 127, jb = tid >> 7;
    char* WvsB = (char*)Wvs;

    {
        const float4* src4 = (const float4*)(obs + (size_t)(b0 + jb) * IN + 4);
        float4* dst4 = (float4*)(ent2 + jb * 2048);
        #pragma unroll
        for (int i = lt; i < 508; i += 128) dst4[i] = src4[i];
        if (lt < 16) ent2[jb * 2048 + 2032 + lt] = 0.f;
    }
    {
        const uint4* wsrc = (const uint4*)g_Wvbf;
        #pragma unroll
        for (int i = tid; i < 1024; i += 256) {
            int row = i >> 3, c = i & 7;
            *(uint4*)(WvsB + SWZ((uint32_t)(row * 128 + c * 16))) = wsrc[i];
        }
    }
    vms2[jb * 256 + lt] = g_vm[(b0 + jb) * 256 + lt];
    vms2[jb * 256 + ((lt + 128) & 255)] = g_vm[(b0 + jb) * 256 + ((lt + 128) & 255)];

    {
        int b = b0 + jb;
        tv2[jb * 128 + lt] = ((lt < 64) ? g_te : g_ta)[b * 64 + (lt & 63)];
        int wl = lt >> 5, lane = lt & 31;
        float t = g_q[b * 256 + wl * 64 + lane]      * g_km[b * 256 + wl * 64 + lane]
                + g_q[b * 256 + wl * 64 + 32 + lane] * g_km[b * 256 + wl * 64 + 32 + lane];
        #pragma unroll
        for (int o = 16; o; o >>= 1) t += __shfl_xor_sync(0xffffffffu, t, o);
        if (lane == 0) whl2[jb * 8 + 4 + wl] = t * 0.125f;
        const float* hrow = g_hid + b * 192;
        float s = 0.f;
        #pragma unroll
        for (int j = lane; j < 128; j += 32) s += hrow[64 + j] * Wh2[wl * 128 + j];
        #pragma unroll
        for (int o = 16; o; o >>= 1) s += __shfl_xor_sync(0xffffffffu, s, o);
        if (lane == 0) whl2[jb * 8 + wl] = fabsf(s + bh2[wl]);
        if (wl == 0) {
            float bsum = hrow[lane] * Wb2[lane] + hrow[32 + lane] * Wb2[32 + lane];
            #pragma unroll
            for (int o = 16; o; o >>= 1) bsum += __shfl_xor_sync(0xffffffffu, bsum, o);
            if (lane == 0) g_bt[b] = bsum + bb2[0];
        }
    }
    __syncthreads();

    const int w = tid >> 5, lane = tid & 31;
    const int sel = w >> 2;
    const int mbase = w * 16;
    const int r = mbase + (lane >> 2);
    const int c0 = (lane & 3) * 2;

    float2 eA[2], eB[2], eC[2], eD[2];
    #pragma unroll
    for (int j = 0; j < 2; j++) {
        const float* ent = ent2 + j * 2048;
        eA[j] = *(float2*)&ent[r * 16 + c0];
        eB[j] = *(float2*)&ent[r * 16 + c0 + 8];
        eC[j] = *(float2*)&ent[(r + 8) * 16 + c0];
        eD[j] = *(float2*)&ent[(r + 8) * 16 + c0 + 8];
    }

    // ---- logits via mma
    {
        int hB = lane >> 2;
        #pragma unroll
        for (int j = 0; j < 2; j++) {
            uint32_t a[4];
            a[0] = packbf2(eA[j].x, eA[j].y);
            a[1] = packbf2(eC[j].x, eC[j].y);
            a[2] = packbf2(eB[j].x, eB[j].y);
            a[3] = packbf2(eD[j].x, eD[j].y);
            uint32_t bfrag[2] = {0u, 0u};
            if (hB < 4) {
                const float* tvb = tv2 + j * 128 + sel * 64 + hB * 16;
                bfrag[0] = packbf2(tvb[c0], tvb[c0 + 1]);
                bfrag[1] = packbf2(tvb[c0 + 8], tvb[c0 + 9]);
            }
            float dl[4] = {0.f, 0.f, 0.f, 0.f};
            MMA16816(dl, a, bfrag);
            float* u = u2 + j * 512;
            if (c0 < 4) {
                if (r < 127) {
                    u[c0 * 128 + 1 + r] = dl[0];
                    u[(c0 + 1) * 128 + 1 + r] = dl[1];
                }
                if (r + 8 < 127) {
                    u[c0 * 128 + 9 + r] = dl[2];
                    u[(c0 + 1) * 128 + 9 + r] = dl[3];
                }
            }
        }
        if (lt < 4) u2[jb * 512 + lt * 128] = whl2[jb * 8 + 4 + lt];
    }
    __syncthreads();

    // ---- softmax
    {
        float* u = u2 + jb * 512;
        int h = lt >> 5, lane2 = lt & 31;
        float v0[4], m0 = -3.4e38f;
        #pragma unroll
        for (int j = 0; j < 4; j++) { v0[j] = u[h * 128 + lane2 + 32 * j]; m0 = fmaxf(m0, v0[j]); }
        #pragma unroll
        for (int o = 16; o; o >>= 1) m0 = fmaxf(m0, __shfl_xor_sync(0xffffffffu, m0, o));
        float ss = 0.f;
        #pragma unroll
        for (int j = 0; j < 4; j++) { v0[j] = expf(v0[j] - m0); ss += v0[j]; }
        #pragma unroll
        for (int o = 16; o; o >>= 1) ss += __shfl_xor_sync(0xffffffffu, ss, o);
        float sc = whl2[jb * 8 + h] / ss;
        #pragma unroll
        for (int j = 0; j < 4; j++) u[h * 128 + lane2 + 32 * j] = v0[j] * sc;
    }
    __syncthreads();

    // ---- tensor-core mix + staged coalesced epilogue
    {
        uint32_t wb = smem_u32(Wvs) + (uint32_t)sel * 8192u;

        float d[2][8][4] = {};
        #pragma unroll
        for (int ks = 0; ks < 4; ks++) {
            uint32_t bfr[8][2];
            #pragma unroll
            for (int nr = 0; nr < 4; nr++) {
                uint32_t byte2 = (uint32_t)((nr * 16 + (lane & 15)) * 128 + (lane >> 4) * 16 + ks * 32);
                uint32_t r0, r1, r2, r3;
                LDSM_X4(r0, r1, r2, r3, wb + SWZ(byte2));
                bfr[nr * 2 + 0][0] = r0; bfr[nr * 2 + 0][1] = r2;
                bfr[nr * 2 + 1][0] = r1; bfr[nr * 2 + 1][1] = r3;
            }
            #pragma unroll
            for (int j = 0; j < 2; j++) {
                const float* u = u2 + j * 512;
                float ul = (r < 127)     ? u[ks * 128 + r + 1] : 0.f;
                float uh = (r + 8 < 127) ? u[ks * 128 + r + 9] : 0.f;
                uint32_t a[4];
                a[0] = packbf2(ul * eA[j].x, ul * eA[j].y);
                a[1] = packbf2(uh * eC[j].x, uh * eC[j].y);
                a[2] = packbf2(ul * eB[j].x, ul * eB[j].y);
                a[3] = packbf2(uh * eD[j].x, uh * eD[j].y);
                #pragma unroll
                for (int nt = 0; nt < 8; nt++) MMA16816(d[j][nt], a, bfr[nt]);
            }
        }

        char* stg = (char*)ent2;
        #pragma unroll
        for (int j = 0; j < 2; j++) {
            __syncthreads();
            if (tid < 64) {
                const float* u = u2 + j * 512;
                const float* vms = vms2 + j * 256;
                float s = 0.f;
                #pragma unroll
                for (int h = 0; h < 4; h++) s += u[h * 128] * vms[h * 64 + tid];
                *(__nv_bfloat16*)(stg + SWZ((uint32_t)(tid * 2))) = __float2bfloat16_rn(s);
            }
            #pragma unroll
            for (int half = 0; half < 2; half++) {
                int Arow = mbase + half * 8 + (lane >> 2);
                if (Arow < 127) {
                    int na = Arow + 1;
                    #pragma unroll
                    for (int nt = 0; nt < 8; nt++) {
                        int e = nt * 8 + (lane & 3) * 2;
                        *(uint32_t*)(stg + SWZ((uint32_t)(na * 128 + e * 2))) =
                            packbf2(d[j][nt][half * 2 + 0], d[j][nt][half * 2 + 1]);
                    }
                }
            }
            __syncthreads();
            uint4* dst = (uint4*)(g_Abf + (size_t)(b0 + j) * KTOT);
            #pragma unroll
            for (int i = tid; i < 1024; i += 256)
                dst[i] = *(uint4*)(stg + SWZ((uint32_t)(i * 16)));
        }
    }
}

// =====================================================================
// K5: bf16 mma GEMM, split-K (gridDim.z=2): partial sums -> g_part{0,1}
// =====================================================================
__global__ __launch_bounds__(256) void k_final_mma() {
    extern __shared__ __align__(128) char smf[];
    const uint32_t sb = smem_u32(smf);
    const int tid = threadIdx.x, lane = tid & 31, w = tid >> 5;
    const int bm = blockIdx.x * 64, bn = blockIdx.y * 128;
    const int kz = blockIdx.z;
    const int tbase = kz * 64;
    const int wm = (w & 1) * 32, wn = (w >> 1) * 32;
    float* part = kz ? g_part1 : g_part0;

    float d[2][4][4] = {};

    auto loadChunk = [&](int t, int s) {
        const __nv_bfloat16* Asrc = g_Abf + (size_t)bm * KTOT + (size_t)(tbase + t) * 64;
        #pragma unroll
        for (int i = 0; i < 2; i++) {
            int idx = tid + 256 * i;
            int row = idx >> 3, c = idx & 7;
            cp16(sb + s * 8192 + SWZ((uint32_t)(row * 128 + c * 16)),
                 Asrc + (size_t)row * KTOT + c * 8);
        }
        const __nv_bfloat16* Bsrc = g_Wfbf + (size_t)bn * KTOT + (size_t)(tbase + t) * 64;
        #pragma unroll
        for (int i = 0; i < 4; i++) {
            int idx = tid + 256 * i;
            int row = idx >> 3, c = idx & 7;
            cp16(sb + 24576 + s * 16384 + SWZ((uint32_t)(row * 128 + c * 16)),
                 Bsrc + (size_t)row * KTOT + c * 8);
        }
        CP_COMMIT();
    };

    loadChunk(0, 0);
    loadChunk(1, 1);
    for (int t = 0; t < 64; t++) {
        const int s = t % 3;
        if (t + 2 < 64)      { loadChunk(t + 2, (t + 2) % 3); CP_WAIT(2); }
        else if (t + 1 < 64) { CP_WAIT(1); }
        else                 { CP_WAIT(0); }
        __syncthreads();

        const uint32_t abase = sb + s * 8192;
        const uint32_t bbase = sb + 24576 + s * 16384;
        #pragma unroll
        for (int ks = 0; ks < 4; ks++) {
            uint32_t a[2][4], b[4][2];
            #pragma unroll
            for (int mt = 0; mt < 2; mt++) {
                uint32_t byte = (uint32_t)((wm + mt * 16 + (lane & 15)) * 128
                                           + (lane >> 4) * 16 + ks * 32);
                LDSM_X4(a[mt][0], a[mt][1], a[mt][2], a[mt][3], abase + SWZ(byte));
            }
            #pragma unroll
            for (int nr = 0; nr < 2; nr++) {
                uint32_t byte = (uint32_t)((wn + nr * 16 + (lane & 15)) * 128
                                           + (lane >> 4) * 16 + ks * 32);
                uint32_t r0, r1, r2, r3;
                LDSM_X4(r0, r1, r2, r3, bbase + SWZ(byte));
                b[nr * 2 + 0][0] = r0; b[nr * 2 + 0][1] = r2;
                b[nr * 2 + 1][0] = r1; b[nr * 2 + 1][1] = r3;
            }
            #pragma unroll
            for (int mt = 0; mt < 2; mt++)
                #pragma unroll
                for (int nt = 0; nt < 4; nt++)
                    MMA16816(d[mt][nt], a[mt], b[nt]);
        }
        __syncthreads();
    }

    const int nbase = bn + wn + (lane & 3) * 2;
    #pragma unroll
    for (int mt = 0; mt < 2; mt++) {
        #pragma unroll
        for (int half = 0; half < 2; half++) {
            int row = bm + wm + mt * 16 + half * 8 + (lane >> 2);
            #pragma unroll
            for (int nt = 0; nt < 4; nt++) {
                int col = nbase + nt * 8;
                *(float2*)&part[(size_t)row * RNN + col] =
                    make_float2(d[mt][nt][half * 2 + 0], d[mt][nt][half * 2 + 1]);
            }
        }
    }
}

// =====================================================================
// K6: out = part0 + part1 + bt*S + bf
// =====================================================================
__global__ __launch_bounds__(256) void k_out(const float* __restrict__ bfv,
                                             float* __restrict__ out) {
    int i = blockIdx.x * 256 + threadIdx.x;       // float4 index, 262144 total
    int row = i >> 6;
    int col4 = (i & 63) * 4;
    float4 p0 = ((const float4*)g_part0)[i];
    float4 p1 = ((const float4*)g_part1)[i];
    float4 sv = *(const float4*)&g_S[col4];
    float4 bv = *(const float4*)&bfv[col4];
    float bt = g_bt[row];
    float4 o;
    o.x = p0.x + p1.x + bt * sv.x + bv.x;
    o.y = p0.y + p1.y + bt * sv.y + bv.y;
    o.z = p0.z + p1.z + bt * sv.z + bv.z;
    o.w = p0.w + p1.w + bt * sv.w + bv.w;
    ((float4*)out)[i] = o;
}

// =====================================================================
// launch
// =====================================================================
extern "C" void kernel_launch(void* const* d_in, const int* in_sizes, int n_in,
                              void* d_out, int out_size) {
    const float* obs  = (const float*)d_in[0];
    const float* Wq1  = (const float*)d_in[1];
    const float* bq1  = (const float*)d_in[2];
    const float* Wq2  = (const float*)d_in[3];
    const float* Wkm1 = (const float*)d_in[4];
    const float* bkm1 = (const float*)d_in[5];
    const float* Wkm2 = (const float*)d_in[6];
    const float* Wke  = (const float*)d_in[7];
    const float* Wka  = (const float*)d_in[8];
    const float* Wvm1 = (const float*)d_in[9];
    const float* bvm1 = (const float*)d_in[10];
    const float* Wvm2 = (const float*)d_in[11];
    const float* Wve  = (const float*)d_in[12];
    const float* Wva  = (const float*)d_in[13];
    const float* Wb1  = (const float*)d_in[14];
    const float* bb1  = (const float*)d_in[15];
    const float* Wb2  = (const float*)d_in[16];
    const float* bb2  = (const float*)d_in[17];
    const float* Wh1  = (const float*)d_in[18];
    const float* bh1  = (const float*)d_in[19];
    const float* Wh2  = (const float*)d_in[20];
    const float* bh2  = (const float*)d_in[21];
    const float* Wf   = (const float*)d_in[22];
    const float* bf   = (const float*)d_in[23];
    float* out = (float*)d_out;

    const int pm_smem = 75264;
    const int final_smem = 24576 + 3 * 16384;
    cudaFuncSetAttribute(k_prep_mlp, cudaFuncAttributeMaxDynamicSharedMemorySize, pm_smem);
    cudaFuncSetAttribute(k_final_mma, cudaFuncAttributeMaxDynamicSharedMemorySize, final_smem);

    k_prep_mlp<<<833, 256, pm_smem>>>(Wf, Wve, Wva, Wb1, Wh1, obs,
                                      Wq1, bq1, Wq2, Wkm1, bkm1, Wkm2,
                                      Wvm1, bvm1, Wvm2, Wke, Wka);
    k_front_tc<<<dim3(64, 3), 256>>>(obs, bb1, bh1);
    k_attn<<<2048, 256>>>(obs, Wb2, bb2, Wh2, bh2);
    k_final_mma<<<dim3(64, 2, 2), 256, final_smem>>>();
    k_out<<<1024, 256>>>(bf, out);
}